// round 9
// baseline (speedup 1.0000x reference)
#include <cuda_runtime.h>
#include <cuda_bf16.h>
#include <math.h>
#include <float.h>
#include <stdint.h>
#include <string.h>

#define B_  4
#define L_  1024
#define D_  512
#define H_  8
#define HD_ 64
#define PROJ_ELEMS (2*B_*H_*L_*HD_)   /* 4,194,304 */
#define MASK_ELEMS ((size_t)B_*L_*L_) /* 4,194,304 */
#define ENC_ELEMS  (8192*512)
#define LOG2E_F 1.4426950408889634f

// producer-split bf16 hi/lo storage
__device__ unsigned short g_ah[ENC_ELEMS], g_al[ENC_ELEMS];      // [u;e] inputs
__device__ unsigned short g_wth[4*512*512], g_wtl[4*512*512];    // W^T, n-major
__device__ unsigned short g_qh[PROJ_ELEMS], g_ql[PROJ_ELEMS];
__device__ unsigned short g_kh[PROJ_ELEMS], g_kl[PROJ_ELEMS];
__device__ unsigned short g_vh[PROJ_ELEMS], g_vl[PROJ_ELEMS];
__device__ unsigned short g_ch[PROJ_ELEMS], g_cl[PROJ_ELEMS];    // ctx hi/lo
__device__ float g_bpp[L_*L_];
__device__ float g_bppT[L_*L_];
__device__ float g_mb[2*B_*L_*L_];       // (bias*log2e) + mask fused
__device__ int g_mtype;

// ===========================================================================
// helpers
// ===========================================================================
__device__ __forceinline__ uint32_t smem_u32(const void* p) {
    uint32_t a;
    asm("{ .reg .u64 t; cvta.to.shared.u64 t, %1; cvt.u32.u64 %0, t; }"
        : "=r"(a) : "l"(p));
    return a;
}
#define CP_ASYNC16(saddr, gptr) \
    asm volatile("cp.async.ca.shared.global [%0], [%1], 16;" \
                 :: "r"(saddr), "l"(gptr))
#define CP_COMMIT() asm volatile("cp.async.commit_group;" ::: "memory")
#define CP_WAIT0()  asm volatile("cp.async.wait_group 0;" ::: "memory")

__device__ __forceinline__ float ex2f(float x) {
    float r;
    asm("ex2.approx.f32 %0, %1;" : "=f"(r) : "f"(x));
    return r;
}
__device__ __forceinline__ void ldsm_x4(uint32_t& r0, uint32_t& r1,
                                        uint32_t& r2, uint32_t& r3,
                                        uint32_t addr) {
    asm volatile("ldmatrix.sync.aligned.m8n8.x4.shared.b16 {%0,%1,%2,%3}, [%4];"
                 : "=r"(r0), "=r"(r1), "=r"(r2), "=r"(r3) : "r"(addr));
}
__device__ __forceinline__ void ldsm_x4_t(uint32_t& r0, uint32_t& r1,
                                          uint32_t& r2, uint32_t& r3,
                                          uint32_t addr) {
    asm volatile("ldmatrix.sync.aligned.m8n8.x4.trans.shared.b16 {%0,%1,%2,%3}, [%4];"
                 : "=r"(r0), "=r"(r1), "=r"(r2), "=r"(r3) : "r"(addr));
}
__device__ __forceinline__ void mma_bf16(float* c, const uint32_t* a,
                                         const uint32_t* b) {
    asm volatile("mma.sync.aligned.m16n8k16.row.col.f32.bf16.bf16.f32 "
                 "{%0,%1,%2,%3}, {%4,%5,%6,%7}, {%8,%9}, {%0,%1,%2,%3};"
                 : "+f"(c[0]), "+f"(c[1]), "+f"(c[2]), "+f"(c[3])
                 : "r"(a[0]), "r"(a[1]), "r"(a[2]), "r"(a[3]),
                   "r"(b[0]), "r"(b[1]));
}
__device__ __forceinline__ unsigned short f2bf_bits(float x) {
    __nv_bfloat16 h = __float2bfloat16(x);
    unsigned short u; memcpy(&u, &h, 2); return u;
}
__device__ __forceinline__ float bfbits2f(unsigned short u) {
    __nv_bfloat16 h; memcpy(&h, &u, 2); return __bfloat162float(h);
}
__device__ __forceinline__ void split2(float x, float y, uint32_t& hi, uint32_t& lo) {
    unsigned short hx = f2bf_bits(x), hy = f2bf_bits(y);
    unsigned short lx = f2bf_bits(x - bfbits2f(hx));
    unsigned short ly = f2bf_bits(y - bfbits2f(hy));
    hi = (uint32_t)hx | ((uint32_t)hy << 16);
    lo = (uint32_t)lx | ((uint32_t)ly << 16);
}

// ===========================================================================
// Mask dtype detection
// ===========================================================================
__global__ void mask_detect_kernel(const unsigned int* __restrict__ m)
{
    __shared__ int viol[3];
    if (threadIdx.x < 3) viol[threadIdx.x] = 0;
    __syncthreads();
    int v0 = 0, v1 = 0, v2 = 0;
    for (int i = threadIdx.x; i < 16384; i += 256) {
        unsigned w = m[i];
        if (w > 1u) v0 = 1;
        if (w != 0u && w != 0x3F800000u) v1 = 1;
        if (w != 0u && w != 0x3F800000u && w != 0x00003F80u && w != 0x3F803F80u) v2 = 1;
    }
    if (v0) atomicOr(&viol[0], 1);
    if (v1) atomicOr(&viol[1], 1);
    if (v2) atomicOr(&viol[2], 1);
    __syncthreads();
    if (threadIdx.x == 0) {
        int t;
        if      (!viol[0]) t = 1;
        else if (!viol[1]) t = 2;
        else if (!viol[2]) t = 3;
        else               t = 0;
        g_mtype = t;
    }
}

// ===========================================================================
// bpp prep
// ===========================================================================
__global__ __launch_bounds__(256) void bpp_prep_kernel(
    const float* __restrict__ lb,
    const float* __restrict__ wp,
    const float* __restrict__ bp)
{
    __shared__ float t[32][33];
    int tx = threadIdx.x, ty = threadIdx.y;
    float w = wp[0], bb = bp[0];
    int x  = blockIdx.x*32 + tx;
    int y0 = blockIdx.y*32;
    #pragma unroll
    for (int i = ty; i < 32; i += 8) {
        float v = fmaf(w, lb[(size_t)(y0+i)*L_ + x], bb);
        g_bpp[(size_t)(y0+i)*L_ + x] = v;
        t[i][tx] = v;
    }
    __syncthreads();
    int xo = y0 + tx;
    #pragma unroll
    for (int i = ty; i < 32; i += 8) {
        g_bppT[(size_t)(blockIdx.x*32+i)*L_ + xo] = t[tx][i];
    }
}

// ===========================================================================
// maskbias (bias scaled by log2e for exp2-domain softmax)
// ===========================================================================
__global__ __launch_bounds__(256) void maskbias_kernel(
    const void* __restrict__ ue, const void* __restrict__ eu)
{
    int t = g_mtype;
    int dir = blockIdx.z;
    const void* src = dir ? eu : ue;
    const float* bp = dir ? g_bppT : g_bpp;
    float* dst = g_mb + (size_t)dir * MASK_ELEMS;
    size_t stride = (size_t)gridDim.x * blockDim.x;
    for (size_t i = (size_t)blockIdx.x*blockDim.x + threadIdx.x;
         i < MASK_ELEMS; i += stride) {
        bool mv;
        if      (t == 1) mv = ((const int*)src)[i] != 0;
        else if (t == 2) mv = ((const float*)src)[i] != 0.f;
        else if (t == 3) mv = ((const unsigned short*)src)[i] != 0;
        else             mv = ((const unsigned char*)src)[i] != 0;
        float bias = bp[i & (L_*L_ - 1)];
        dst[i] = mv ? bias * LOG2E_F : -1.0e38f;
    }
}

// ===========================================================================
// enc split
// ===========================================================================
__global__ __launch_bounds__(256) void enc_split_kernel(
    const float* __restrict__ u, const float* __restrict__ e)
{
    const float* src = blockIdx.z ? e : u;
    size_t base4 = (size_t)blockIdx.z * (4096*512/4);
    size_t stride = (size_t)gridDim.x * blockDim.x;
    for (size_t i4 = (size_t)blockIdx.x*blockDim.x + threadIdx.x;
         i4 < 4096*512/4; i4 += stride) {
        float4 v = ((const float4*)src)[i4];
        uint32_t h01, l01, h23, l23;
        split2(v.x, v.y, h01, l01);
        split2(v.z, v.w, h23, l23);
        ((uint2*)g_ah)[base4 + i4] = make_uint2(h01, h23);
        ((uint2*)g_al)[base4 + i4] = make_uint2(l01, l23);
    }
}

// ===========================================================================
// weight transpose+split
// ===========================================================================
__global__ __launch_bounds__(256) void wt_split_kernel(
    const float* __restrict__ wq, const float* __restrict__ wk,
    const float* __restrict__ wv, const float* __restrict__ wo)
{
    const float* src = (blockIdx.z == 0) ? wq : (blockIdx.z == 1) ? wk
                     : (blockIdx.z == 2) ? wv : wo;
    __shared__ float t[32][33];
    int tx = threadIdx.x, ty = threadIdx.y;
    int x  = blockIdx.x*32 + tx;
    int y0 = blockIdx.y*32;
    #pragma unroll
    for (int i = ty; i < 32; i += 8)
        t[i][tx] = src[(size_t)(y0+i)*512 + x];
    __syncthreads();
    size_t base = (size_t)blockIdx.z * 512*512;
    int ko = y0 + tx;
    #pragma unroll
    for (int i = ty; i < 32; i += 8) {
        float v = t[tx][i];
        unsigned short h = f2bf_bits(v);
        unsigned short l = f2bf_bits(v - bfbits2f(h));
        size_t idx = base + (size_t)(blockIdx.x*32+i)*512 + ko;
        g_wth[idx] = h;
        g_wtl[idx] = l;
    }
}

// ===========================================================================
// GEMM: 128M x 128N tiles (halves A traffic), cp.async double-buffered.
//   256 threads (8 warps, 4x2). Warp tile 32M x 64N.
// Stage: AH 0 (18432), AL 18432, BH 36864 (18432), BL 55296; 73728/stage.
// ===========================================================================
#define GM_BUF  73728
#define GM_AH   0
#define GM_AL   18432
#define GM_BH   36864
#define GM_BL   55296
#define GM_SMEM 147456

__global__ __launch_bounds__(256) void gemm_mma_kernel(
    const float* __restrict__ bq, const float* __restrict__ bk,
    const float* __restrict__ bv, const float* __restrict__ bo,
    float* __restrict__ outp, int modebase)
{
    extern __shared__ __align__(16) unsigned char smem[];
    uint32_t sbase = smem_u32(smem);

    int tid = threadIdx.x;
    int wid = tid >> 5, lane = tid & 31;
    int wm = wid & 3, wn = wid >> 2;

    int mode = modebase + blockIdx.z;
    const float* bias;
    unsigned short *dsth, *dstl;
    if      (mode == 0) { bias = bq; dsth = g_qh; dstl = g_ql; }
    else if (mode == 1) { bias = bk; dsth = g_kh; dstl = g_kl; }
    else if (mode == 2) { bias = bv; dsth = g_vh; dstl = g_vl; }
    else                { bias = bo; dsth = 0;    dstl = 0;    }

    const unsigned short* Ah = (mode < 3) ? g_ah : g_ch;
    const unsigned short* Al = (mode < 3) ? g_al : g_cl;
    int widx = (mode < 3) ? mode : 3;
    const unsigned short* Bh = g_wth + (size_t)widx*512*512;
    const unsigned short* Bl = g_wtl + (size_t)widx*512*512;

    int n0   = blockIdx.x * 128;
    int row0 = blockIdx.y * 128;

    float acc[2][8][4];
    #pragma unroll
    for (int mi = 0; mi < 2; mi++)
        #pragma unroll
        for (int ni = 0; ni < 8; ni++)
            #pragma unroll
            for (int c = 0; c < 4; c++) acc[mi][ni][c] = 0.f;

    auto issue_chunk = [&](int kb, uint32_t bufo) {
        int kbase = kb * 64;
        // A: 128 rows x 8 uint4 x 2 arrays = 2048 uint4 / 256 thr = 8 iters
        #pragma unroll
        for (int i = 0; i < 8; i++) {
            int idx = i*256 + tid;
            int a = idx >> 10;
            int rem = idx & 1023;
            int row = rem >> 3, q8 = rem & 7;
            const unsigned short* srcp = a ? Al : Ah;
            CP_ASYNC16(sbase + bufo + (a ? GM_AL : GM_AH) + row*144 + q8*16,
                       &srcp[(size_t)(row0+row)*512 + kbase + q8*8]);
        }
        // B: 128 n-rows x 8 uint4 x 2 arrays = 2048 uint4 = 8 iters
        #pragma unroll
        for (int i = 0; i < 8; i++) {
            int idx = i*256 + tid;
            int a = idx >> 10;
            int rem = idx & 1023;
            int row = rem >> 3, q8 = rem & 7;
            const unsigned short* srcp = a ? Bl : Bh;
            CP_ASYNC16(sbase + bufo + (a ? GM_BL : GM_BH) + row*144 + q8*16,
                       &srcp[(size_t)(n0+row)*512 + kbase + q8*8]);
        }
        CP_COMMIT();
    };

    issue_chunk(0, 0);

    for (int kb = 0; kb < 8; kb++) {
        uint32_t bufo = (kb & 1) ? GM_BUF : 0;
        CP_WAIT0();
        __syncthreads();
        if (kb + 1 < 8)
            issue_chunk(kb + 1, ((kb + 1) & 1) ? GM_BUF : 0);

        #pragma unroll
        for (int ks = 0; ks < 4; ks++) {
            uint32_t a_hi[2][4], a_lo[2][4], b_hi[4][4], b_lo[4][4];
            #pragma unroll
            for (int mi = 0; mi < 2; mi++) {
                int row = wm*32 + mi*16 + (lane & 15);
                int kcol = ks*16 + ((lane >> 4) << 3);
                uint32_t off = bufo + (uint32_t)(row*144 + kcol*2);
                ldsm_x4(a_hi[mi][0], a_hi[mi][1], a_hi[mi][2], a_hi[mi][3],
                        sbase + GM_AH + off);
                ldsm_x4(a_lo[mi][0], a_lo[mi][1], a_lo[mi][2], a_lo[mi][3],
                        sbase + GM_AL + off);
            }
            #pragma unroll
            for (int g = 0; g < 4; g++) {
                int rr = lane & 7;
                int hk = (lane >> 3) & 1;
                int hn = (lane >> 4) & 1;
                int nrow = wn*64 + g*16 + hn*8 + rr;
                int kcol = ks*16 + hk*8;
                uint32_t off = bufo + (uint32_t)(nrow*144 + kcol*2);
                ldsm_x4(b_hi[g][0], b_hi[g][1], b_hi[g][2], b_hi[g][3],
                        sbase + GM_BH + off);
                ldsm_x4(b_lo[g][0], b_lo[g][1], b_lo[g][2], b_lo[g][3],
                        sbase + GM_BL + off);
            }
            // term-outer: 16 independent accumulators between same-acc reuses
            #pragma unroll
            for (int mi = 0; mi < 2; mi++)
                #pragma unroll
                for (int ni = 0; ni < 8; ni++)
                    mma_bf16(acc[mi][ni], a_hi[mi], &b_hi[ni>>1][(ni&1)*2]);
            #pragma unroll
            for (int mi = 0; mi < 2; mi++)
                #pragma unroll
                for (int ni = 0; ni < 8; ni++)
                    mma_bf16(acc[mi][ni], a_lo[mi], &b_hi[ni>>1][(ni&1)*2]);
            #pragma unroll
            for (int mi = 0; mi < 2; mi++)
                #pragma unroll
                for (int ni = 0; ni < 8; ni++)
                    mma_bf16(acc[mi][ni], a_hi[mi], &b_lo[ni>>1][(ni&1)*2]);
        }
    }

    float scale = (mode == 0) ? 0.125f * LOG2E_F : 1.f;
    #pragma unroll
    for (int mi = 0; mi < 2; mi++) {
        #pragma unroll
        for (int ni = 0; ni < 8; ni++) {
            int nglob = n0 + wn*64 + ni*8 + (lane & 3)*2;
            float b0 = bias[nglob], b1 = bias[nglob + 1];
            #pragma unroll
            for (int half = 0; half < 2; half++) {
                int m = row0 + wm*32 + mi*16 + (lane >> 2) + half*8;
                float ox = (acc[mi][ni][half*2+0] + b0) * scale;
                float oy = (acc[mi][ni][half*2+1] + b1) * scale;
                if (mode < 3) {
                    int enc = m >> 12, b = (m >> 10) & 3, l = m & 1023;
                    int h = nglob >> 6;
                    size_t idx = ((((size_t)(enc*B_ + b))*H_ + h)*L_ + l)*HD_
                                 + (nglob & 63);
                    uint32_t hi, lo;
                    split2(ox, oy, hi, lo);
                    *(uint32_t*)&dsth[idx] = hi;
                    *(uint32_t*)&dstl[idx] = lo;
                } else {
                    float2 o; o.x = ox; o.y = oy;
                    *(float2*)&outp[(size_t)m*D_ + nglob] = o;
                }
            }
        }
    }
}

// ===========================================================================
// Flash attention: 128 q-rows per CTA (8 warps, 256 thr) — halves KV traffic.
//   grid (8 qtiles, 32 b*h, 2 dirs). Warp w owns q rows [w*16, w*16+16).
// KV ring (2 stages of 36864): KH 0, KL 9216, VH 18432, VL 27648.
// Q region at 73728: QH (18432) + QL (18432). Total smem 110592.
// ===========================================================================
#define AT_BUF  36864
#define AT_KH   0
#define AT_KL   9216
#define AT_VH   18432
#define AT_VL   27648
#define AT_Q    73728
#define AT_SMEM 110592

__global__ __launch_bounds__(256) void attn_mma_kernel()
{
    extern __shared__ __align__(16) unsigned char smem[];
    uint32_t sbase = smem_u32(smem);

    int tid = threadIdx.x;
    int wid = tid >> 5, lane = tid & 31;
    int r = lane >> 2, cq = lane & 3;

    int qt = blockIdx.x, bh = blockIdx.y, dir = blockIdx.z;
    int b = bh >> 3, h = bh & 7;
    int enc_q = dir, enc_kv = 1 - dir;

    size_t qoff  = ((size_t)((enc_q *B_ + b)*H_ + h))*L_*HD_;
    size_t kvoff = ((size_t)((enc_kv*B_ + b)*H_ + h))*L_*HD_;
    const unsigned short* Qh = g_qh + qoff;
    const unsigned short* Ql = g_ql + qoff;
    const unsigned short* Kh = g_kh + kvoff;
    const unsigned short* Kl = g_kl + kvoff;
    const unsigned short* Vh = g_vh + kvoff;
    const unsigned short* Vl = g_vl + kvoff;
    const float* mb = g_mb + ((size_t)dir*B_ + b)*L_*L_;
    int q0 = qt * 128;

    // ---- Q cp.async: 128 rows x 8 uint4 x 2 arrays = 2048 uint4 / 256 thr ----
    #pragma unroll
    for (int i = 0; i < 8; i++) {
        int idx = i*256 + tid;
        int a = idx >> 10;
        int rem = idx & 1023;
        int row = rem >> 3, q8 = rem & 7;
        const unsigned short* srcp = a ? Ql : Qh;
        CP_ASYNC16(sbase + AT_Q + (a ? 18432 : 0) + row*144 + q8*16,
                   &srcp[(size_t)(q0+row)*HD_ + q8*8]);
    }
    CP_COMMIT();
    CP_WAIT0();
    __syncthreads();

    auto issue_kv = [&](int t, uint32_t bufo) {
        int k0 = t * 64;
        // 64 keys x 8 uint4 x 4 arrays = 2048 uint4 / 256 thr = 8 iters
        #pragma unroll
        for (int i = 0; i < 8; i++) {
            int idx = i*256 + tid;
            int a = idx >> 9;                  // 0=KH 1=KL 2=VH 3=VL
            int rem = idx & 511;
            int row = rem >> 3, q8 = rem & 7;
            const unsigned short* srcp = (a == 0) ? Kh : (a == 1) ? Kl
                                       : (a == 2) ? Vh : Vl;
            int dsto = (a == 0) ? AT_KH : (a == 1) ? AT_KL
                     : (a == 2) ? AT_VH : AT_VL;
            CP_ASYNC16(sbase + bufo + dsto + row*144 + q8*16,
                       &srcp[(size_t)(k0+row)*HD_ + q8*8]);
        }
        CP_COMMIT();
    };

    issue_kv(0, 0);

    // ---- Q A-fragments resident in regs ----
    uint32_t aq_h[4][4], aq_l[4][4];
    #pragma unroll
    for (int ks = 0; ks < 4; ks++) {
        int row = wid*16 + (lane & 15);
        int kcol = ks*16 + ((lane >> 4) << 3);
        uint32_t off = (uint32_t)(row*144 + kcol*2);
        ldsm_x4(aq_h[ks][0], aq_h[ks][1], aq_h[ks][2], aq_h[ks][3],
                sbase + AT_Q + off);
        ldsm_x4(aq_l[ks][0], aq_l[ks][1], aq_l[ks][2], aq_l[ks][3],
                sbase + AT_Q + 18432 + off);
    }

    float o_acc[8][4];
    #pragma unroll
    for (int nt = 0; nt < 8; nt++)
        #pragma unroll
        for (int c = 0; c < 4; c++) o_acc[nt][c] = 0.f;
    float m0r = -3.0e38f, m1r = -3.0e38f, l0r = 0.f, l1r = 0.f;

    int qg0 = q0 + wid*16 + r;
    int qg1 = qg0 + 8;
    const float* mb0 = mb + (size_t)qg0*L_ + cq*2;
    const float* mb1 = mb + (size_t)qg1*L_ + cq*2;

    for (int t = 0; t < 16; t++) {
        int k0 = t * 64;
        uint32_t bufo = (t & 1) ? AT_BUF : 0;
        CP_WAIT0();
        __syncthreads();
        if (t + 1 < 16)
            issue_kv(t + 1, ((t + 1) & 1) ? AT_BUF : 0);

        float2 mbv0[8], mbv1[8];
        #pragma unroll
        for (int nt = 0; nt < 8; nt++) {
            int cc = k0 + nt*8;
            mbv0[nt] = *(const float2*)&mb0[cc];
            mbv1[nt] = *(const float2*)&mb1[cc];
        }

        // ---- S = Q K^T ----
        float s_acc[8][4];
        #pragma unroll
        for (int nt = 0; nt < 8; nt++)
            #pragma unroll
            for (int c = 0; c < 4; c++) s_acc[nt][c] = 0.f;

        #pragma unroll
        for (int ks = 0; ks < 4; ks++) {
            #pragma unroll
            for (int g = 0; g < 4; g++) {
                uint32_t bk_h[4], bk_l[4];
                int rr = lane & 7;
                int hk = (lane >> 3) & 1;
                int hn = (lane >> 4) & 1;
                int nrow = g*16 + hn*8 + rr;
                int kcol = ks*16 + hk*8;
                uint32_t off = bufo + (uint32_t)(nrow*144 + kcol*2);
                ldsm_x4(bk_h[0], bk_h[1], bk_h[2], bk_h[3], sbase + AT_KH + off);
                ldsm_x4(bk_l[0], bk_l[1], bk_l[2], bk_l[3], sbase + AT_KL + off);
                int n0t = g*2, n1t = g*2 + 1;
                mma_bf16(s_acc[n0t], aq_h[ks], &bk_h[0]);
                mma_bf16(s_acc[n1t], aq_h[ks], &bk_h[2]);
                mma_bf16(s_acc[n0t], aq_l[ks], &bk_h[0]);
                mma_bf16(s_acc[n1t], aq_l[ks], &bk_h[2]);
                mma_bf16(s_acc[n0t], aq_h[ks], &bk_l[0]);
                mma_bf16(s_acc[n1t], aq_h[ks], &bk_l[2]);
            }
        }

        // ---- additive mask+bias (log2 domain) ----
        #pragma unroll
        for (int nt = 0; nt < 8; nt++) {
            s_acc[nt][0] += mbv0[nt].x;
            s_acc[nt][1] += mbv0[nt].y;
            s_acc[nt][2] += mbv1[nt].x;
            s_acc[nt][3] += mbv1[nt].y;
        }

        // ---- online softmax (base-2) ----
        float mx0 = -3.0e38f, mx1 = -3.0e38f;
        #pragma unroll
        for (int nt = 0; nt < 8; nt++) {
            mx0 = fmaxf(mx0, fmaxf(s_acc[nt][0], s_acc[nt][1]));
            mx1 = fmaxf(mx1, fmaxf(s_acc[nt][2], s_acc[nt][3]));
        }
        mx0 = fmaxf(mx0, __shfl_xor_sync(0xffffffffu, mx0, 1));
        mx0 = fmaxf(mx0, __shfl_xor_sync(0xffffffffu, mx0, 2));
        mx1 = fmaxf(mx1, __shfl_xor_sync(0xffffffffu, mx1, 1));
        mx1 = fmaxf(mx1, __shfl_xor_sync(0xffffffffu, mx1, 2));

        float mn0 = fmaxf(m0r, mx0);
        float mn1 = fmaxf(m1r, mx1);
        float c0 = ex2f(m0r - mn0);
        float c1 = ex2f(m1r - mn1);
        m0r = mn0; m1r = mn1;

        float rs0 = 0.f, rs1 = 0.f;
        #pragma unroll
        for (int nt = 0; nt < 8; nt++) {
            s_acc[nt][0] = ex2f(s_acc[nt][0] - m0r); rs0 += s_acc[nt][0];
            s_acc[nt][1] = ex2f(s_acc[nt][1] - m0r); rs0 += s_acc[nt][1];
            s_acc[nt][2] = ex2f(s_acc[nt][2] - m1r); rs1 += s_acc[nt][2];
            s_acc[nt][3] = ex2f(s_acc[nt][3] - m1r); rs1 += s_acc[nt][3];
        }
        rs0 += __shfl_xor_sync(0xffffffffu, rs0, 1);
        rs0 += __shfl_xor_sync(0xffffffffu, rs0, 2);
        rs1 += __shfl_xor_sync(0xffffffffu, rs1, 1);
        rs1 += __shfl_xor_sync(0xffffffffu, rs1, 2);
        l0r = l0r*c0 + rs0;
        l1r = l1r*c1 + rs1;

        #pragma unroll
        for (int nt = 0; nt < 8; nt++) {
            o_acc[nt][0] *= c0; o_acc[nt][1] *= c0;
            o_acc[nt][2] *= c1; o_acc[nt][3] *= c1;
        }

        // ---- O += P V ----
        #pragma unroll
        for (int ks = 0; ks < 4; ks++) {
            int t0 = 2*ks, t1 = 2*ks + 1;
            uint32_t ap_h[4], ap_l[4];
            split2(s_acc[t0][0], s_acc[t0][1], ap_h[0], ap_l[0]);
            split2(s_acc[t0][2], s_acc[t0][3], ap_h[1], ap_l[1]);
            split2(s_acc[t1][0], s_acc[t1][1], ap_h[2], ap_l[2]);
            split2(s_acc[t1][2], s_acc[t1][3], ap_h[3], ap_l[3]);
            #pragma unroll
            for (int g = 0; g < 4; g++) {
                uint32_t bv_h[4], bv_l[4];
                int kk  = ks*16 + ((lane >> 3) & 1)*8 + (lane & 7);
                int hdo = g*16 + ((lane >> 4) & 1)*8;
                uint32_t off = bufo + (uint32_t)(kk*144 + hdo*2);
                ldsm_x4_t(bv_h[0], bv_h[1], bv_h[2], bv_h[3], sbase + AT_VH + off);
                ldsm_x4_t(bv_l[0], bv_l[1], bv_l[2], bv_l[3], sbase + AT_VL + off);
                int n0t = g*2, n1t = g*2 + 1;
                mma_bf16(o_acc[n0t], ap_h, &bv_h[0]);
                mma_bf16(o_acc[n1t], ap_h, &bv_h[2]);
                mma_bf16(o_acc[n0t], ap_l, &bv_h[0]);
                mma_bf16(o_acc[n1t], ap_l, &bv_h[2]);
                mma_bf16(o_acc[n0t], ap_h, &bv_l[0]);
                mma_bf16(o_acc[n1t], ap_h, &bv_l[2]);
            }
        }
    }

    // ---- finalize ----
    float inv0 = 1.f / l0r;
    float inv1 = 1.f / l1r;
    size_t base0 = ((size_t)(enc_q*B_ + b)*L_ + qg0)*D_ + h*64 + cq*2;
    size_t base1 = ((size_t)(enc_q*B_ + b)*L_ + qg1)*D_ + h*64 + cq*2;
    #pragma unroll
    for (int nt = 0; nt < 8; nt++) {
        uint32_t hi0, lo0, hi1, lo1;
        split2(o_acc[nt][0]*inv0, o_acc[nt][1]*inv0, hi0, lo0);
        split2(o_acc[nt][2]*inv1, o_acc[nt][3]*inv1, hi1, lo1);
        *(uint32_t*)&g_ch[base0 + nt*8] = hi0;
        *(uint32_t*)&g_cl[base0 + nt*8] = lo0;
        *(uint32_t*)&g_ch[base1 + nt*8] = hi1;
        *(uint32_t*)&g_cl[base1 + nt*8] = lo1;
    }
}

// ---------------------------------------------------------------------------
extern "C" void kernel_launch(void* const* d_in, const int* in_sizes, int n_in,
                              void* d_out, int out_size)
{
    const float* u_enc     = (const float*)d_in[0];
    const float* e_enc     = (const float*)d_in[1];
    const float* logit_bpp = (const float*)d_in[2];
    const void*  ue_mask   = d_in[3];
    const void*  eu_mask   = d_in[4];
    const float* wq_k = (const float*)d_in[5];
    const float* wq_b = (const float*)d_in[6];
    const float* wk_k = (const float*)d_in[7];
    const float* wk_b = (const float*)d_in[8];
    const float* wv_k = (const float*)d_in[9];
    const float* wv_b = (const float*)d_in[10];
    const float* wo_k = (const float*)d_in[11];
    const float* wo_b = (const float*)d_in[12];
    const float* bpp_w = (const float*)d_in[13];
    const float* bpp_b = (const float*)d_in[14];
    float* out = (float*)d_out;

    cudaFuncSetAttribute((const void*)attn_mma_kernel,
                         cudaFuncAttributeMaxDynamicSharedMemorySize, AT_SMEM);
    cudaFuncSetAttribute((const void*)gemm_mma_kernel,
                         cudaFuncAttributeMaxDynamicSharedMemorySize, GM_SMEM);

    // 0) mask dtype detection
    mask_detect_kernel<<<1, 256>>>((const unsigned int*)ue_mask);
    // 1) bias prep then fused mask+bias (log2e-scaled)
    bpp_prep_kernel<<<dim3(32, 32), dim3(32, 8)>>>(logit_bpp, bpp_w, bpp_b);
    maskbias_kernel<<<dim3(4096, 1, 2), 256>>>(ue_mask, eu_mask);
    // 2) one-time operand splits
    enc_split_kernel<<<dim3(1024, 1, 2), 256>>>(u_enc, e_enc);
    wt_split_kernel<<<dim3(16, 16, 4), dim3(32, 8)>>>(wq_k, wk_k, wv_k, wo_k);
    // 3) fused QKV projections (128x128 tiles; q scaled by 0.125*log2e)
    gemm_mma_kernel<<<dim3(4, 64, 3), 256, GM_SMEM>>>(wq_b, wk_b, wv_b, wo_b,
                                                      nullptr, 0);
    // 4) fused attention (128 q-rows/CTA)
    attn_mma_kernel<<<dim3(8, 32, 2), 256, AT_SMEM>>>();
    // 5) output projection -> d_out
    gemm_mma_kernel<<<dim3(4, 64, 1), 256, GM_SMEM>>>(wq_b, wk_b, wv_b, wo_b,
                                                      out, 3);
}

// round 10
// speedup vs baseline: 1.3098x; 1.3098x over previous
#include <cuda_runtime.h>
#include <cuda_fp16.h>
#include <math.h>
#include <float.h>
#include <stdint.h>
#include <string.h>

#define B_  4
#define L_  1024
#define D_  512
#define H_  8
#define HD_ 64
#define PROJ_ELEMS (2*B_*H_*L_*HD_)   /* 4,194,304 */
#define MASK_ELEMS ((size_t)B_*L_*L_) /* 4,194,304 */
#define ENC_ELEMS  (8192*512)
#define LOG2E_F 1.4426950408889634f

// producer-split fp16 hi/lo storage
__device__ unsigned short g_ah[ENC_ELEMS], g_al[ENC_ELEMS];      // [u;e] inputs
__device__ unsigned short g_wth[4*512*512], g_wtl[4*512*512];    // W^T, n-major
__device__ unsigned short g_qh[PROJ_ELEMS], g_ql[PROJ_ELEMS];
__device__ unsigned short g_kh[PROJ_ELEMS], g_kl[PROJ_ELEMS];
__device__ unsigned short g_vh[PROJ_ELEMS];                      // V single fp16
__device__ unsigned short g_ch[PROJ_ELEMS], g_cl[PROJ_ELEMS];    // ctx hi/lo
__device__ float g_mb[2*B_*L_*L_];       // (bias*log2e) + mask fused
__device__ int g_mtype;

// ===========================================================================
// helpers
// ===========================================================================
__device__ __forceinline__ uint32_t smem_u32(const void* p) {
    uint32_t a;
    asm("{ .reg .u64 t; cvta.to.shared.u64 t, %1; cvt.u32.u64 %0, t; }"
        : "=r"(a) : "l"(p));
    return a;
}
#define CP_ASYNC16(saddr, gptr) \
    asm volatile("cp.async.ca.shared.global [%0], [%1], 16;" \
                 :: "r"(saddr), "l"(gptr))
#define CP_COMMIT() asm volatile("cp.async.commit_group;" ::: "memory")
#define CP_WAIT0()  asm volatile("cp.async.wait_group 0;" ::: "memory")

__device__ __forceinline__ float ex2f(float x) {
    float r;
    asm("ex2.approx.f32 %0, %1;" : "=f"(r) : "f"(x));
    return r;
}
__device__ __forceinline__ void ldsm_x4(uint32_t& r0, uint32_t& r1,
                                        uint32_t& r2, uint32_t& r3,
                                        uint32_t addr) {
    asm volatile("ldmatrix.sync.aligned.m8n8.x4.shared.b16 {%0,%1,%2,%3}, [%4];"
                 : "=r"(r0), "=r"(r1), "=r"(r2), "=r"(r3) : "r"(addr));
}
__device__ __forceinline__ void ldsm_x4_t(uint32_t& r0, uint32_t& r1,
                                          uint32_t& r2, uint32_t& r3,
                                          uint32_t addr) {
    asm volatile("ldmatrix.sync.aligned.m8n8.x4.trans.shared.b16 {%0,%1,%2,%3}, [%4];"
                 : "=r"(r0), "=r"(r1), "=r"(r2), "=r"(r3) : "r"(addr));
}
__device__ __forceinline__ void mma_f16(float* c, const uint32_t* a,
                                        const uint32_t* b) {
    asm volatile("mma.sync.aligned.m16n8k16.row.col.f32.f16.f16.f32 "
                 "{%0,%1,%2,%3}, {%4,%5,%6,%7}, {%8,%9}, {%0,%1,%2,%3};"
                 : "+f"(c[0]), "+f"(c[1]), "+f"(c[2]), "+f"(c[3])
                 : "r"(a[0]), "r"(a[1]), "r"(a[2]), "r"(a[3]),
                   "r"(b[0]), "r"(b[1]));
}
__device__ __forceinline__ unsigned short f2h_bits(float x) {
    __half h = __float2half_rn(x);
    unsigned short u; memcpy(&u, &h, 2); return u;
}
__device__ __forceinline__ float hbits2f(unsigned short u) {
    __half h; memcpy(&h, &u, 2); return __half2float(h);
}
__device__ __forceinline__ void split2(float x, float y, uint32_t& hi, uint32_t& lo) {
    unsigned short hx = f2h_bits(x), hy = f2h_bits(y);
    unsigned short lx = f2h_bits(x - hbits2f(hx));
    unsigned short ly = f2h_bits(y - hbits2f(hy));
    hi = (uint32_t)hx | ((uint32_t)hy << 16);
    lo = (uint32_t)lx | ((uint32_t)ly << 16);
}
__device__ __forceinline__ uint32_t pack2h(float x, float y) {
    return (uint32_t)f2h_bits(x) | ((uint32_t)f2h_bits(y) << 16);
}

// ===========================================================================
// Mask dtype detection
// ===========================================================================
__global__ void mask_detect_kernel(const unsigned int* __restrict__ m)
{
    __shared__ int viol[3];
    if (threadIdx.x < 3) viol[threadIdx.x] = 0;
    __syncthreads();
    int v0 = 0, v1 = 0, v2 = 0;
    for (int i = threadIdx.x; i < 16384; i += 256) {
        unsigned w = m[i];
        if (w > 1u) v0 = 1;
        if (w != 0u && w != 0x3F800000u) v1 = 1;
        if (w != 0u && w != 0x3F800000u && w != 0x00003F80u && w != 0x3F803F80u) v2 = 1;
    }
    if (v0) atomicOr(&viol[0], 1);
    if (v1) atomicOr(&viol[1], 1);
    if (v2) atomicOr(&viol[2], 1);
    __syncthreads();
    if (threadIdx.x == 0) {
        int t;
        if      (!viol[0]) t = 1;
        else if (!viol[1]) t = 2;
        else if (!viol[2]) t = 3;
        else               t = 0;
        g_mtype = t;
    }
}

// ===========================================================================
// fused maskbias: g_mb[dir][b][q][k] = mask ? (w*lb(+T)+b)*log2e : -1e38
// grid (32,32,2) block (32,8); dir1 transposes lb through smem.
// ===========================================================================
__global__ __launch_bounds__(256) void maskbias_kernel(
    const float* __restrict__ lb,
    const float* __restrict__ wp, const float* __restrict__ bp,
    const void* __restrict__ ue, const void* __restrict__ eu)
{
    __shared__ float s[32][33];
    int tx = threadIdx.x, ty = threadIdx.y;
    int dir = blockIdx.z;
    int mt = g_mtype;
    float w = wp[0] * LOG2E_F, bb = bp[0] * LOG2E_F;
    int k0 = blockIdx.x*32, q0 = blockIdx.y*32;
    const void* msk = dir ? eu : ue;
    float* dst = g_mb + (size_t)dir * MASK_ELEMS;

    if (dir == 1) {
        // need lb[k][q]: load tile rows=k, cols=q coalesced
        #pragma unroll
        for (int i = ty; i < 32; i += 8)
            s[i][tx] = lb[(size_t)(k0+i)*L_ + q0 + tx];
        __syncthreads();
    }

    #pragma unroll
    for (int i = ty; i < 32; i += 8) {
        float bias;
        if (dir == 0) bias = fmaf(w, lb[(size_t)(q0+i)*L_ + k0 + tx], bb);
        else          bias = fmaf(w, s[tx][i], bb);
        size_t rowoff = (size_t)(q0+i)*L_ + k0 + tx;
        #pragma unroll
        for (int b = 0; b < B_; b++) {
            size_t idx = ((size_t)b << 20) + rowoff;
            bool mv;
            if      (mt == 1) mv = ((const int*)msk)[idx] != 0;
            else if (mt == 2) mv = ((const float*)msk)[idx] != 0.f;
            else if (mt == 3) mv = ((const unsigned short*)msk)[idx] != 0;
            else              mv = ((const unsigned char*)msk)[idx] != 0;
            dst[idx] = mv ? bias : -1.0e38f;
        }
    }
}

// ===========================================================================
// enc split (fp16 hi/lo)
// ===========================================================================
__global__ __launch_bounds__(256) void enc_split_kernel(
    const float* __restrict__ u, const float* __restrict__ e)
{
    const float* src = blockIdx.z ? e : u;
    size_t base4 = (size_t)blockIdx.z * (4096*512/4);
    size_t stride = (size_t)gridDim.x * blockDim.x;
    for (size_t i4 = (size_t)blockIdx.x*blockDim.x + threadIdx.x;
         i4 < 4096*512/4; i4 += stride) {
        float4 v = ((const float4*)src)[i4];
        uint32_t h01, l01, h23, l23;
        split2(v.x, v.y, h01, l01);
        split2(v.z, v.w, h23, l23);
        ((uint2*)g_ah)[base4 + i4] = make_uint2(h01, h23);
        ((uint2*)g_al)[base4 + i4] = make_uint2(l01, l23);
    }
}

// ===========================================================================
// weight transpose+split (fp16 hi/lo)
// ===========================================================================
__global__ __launch_bounds__(256) void wt_split_kernel(
    const float* __restrict__ wq, const float* __restrict__ wk,
    const float* __restrict__ wv, const float* __restrict__ wo)
{
    const float* src = (blockIdx.z == 0) ? wq : (blockIdx.z == 1) ? wk
                     : (blockIdx.z == 2) ? wv : wo;
    __shared__ float t[32][33];
    int tx = threadIdx.x, ty = threadIdx.y;
    int x  = blockIdx.x*32 + tx;
    int y0 = blockIdx.y*32;
    #pragma unroll
    for (int i = ty; i < 32; i += 8)
        t[i][tx] = src[(size_t)(y0+i)*512 + x];
    __syncthreads();
    size_t base = (size_t)blockIdx.z * 512*512;
    int ko = y0 + tx;
    #pragma unroll
    for (int i = ty; i < 32; i += 8) {
        float v = t[tx][i];
        unsigned short h = f2h_bits(v);
        unsigned short l = f2h_bits(v - hbits2f(h));
        size_t idx = base + (size_t)(blockIdx.x*32+i)*512 + ko;
        g_wth[idx] = h;
        g_wtl[idx] = l;
    }
}

// ===========================================================================
// GEMM: 128M x 64N, K chunks 64, cp.async double-buffered.
// QKV (mode<3): 3-term split. out-proj (mode 3): 2-term (skip hl pass).
// ===========================================================================
#define GM_BUF  55296
#define GM_AH   0
#define GM_AL   18432
#define GM_BH   36864
#define GM_BL   46080
#define GM_SMEM 110592

__global__ __launch_bounds__(256) void gemm_mma_kernel(
    const float* __restrict__ bq, const float* __restrict__ bk,
    const float* __restrict__ bv, const float* __restrict__ bo,
    float* __restrict__ outp, int modebase)
{
    extern __shared__ __align__(16) unsigned char smem[];
    uint32_t sbase = smem_u32(smem);

    int tid = threadIdx.x;
    int wid = tid >> 5, lane = tid & 31;
    int wm = wid & 3, wn = wid >> 2;

    int mode = modebase + blockIdx.z;
    const float* bias;
    if      (mode == 0) bias = bq;
    else if (mode == 1) bias = bk;
    else if (mode == 2) bias = bv;
    else                bias = bo;

    const unsigned short* Ah = (mode < 3) ? g_ah : g_ch;
    const unsigned short* Al = (mode < 3) ? g_al : g_cl;
    int widx = (mode < 3) ? mode : 3;
    const unsigned short* Bh = g_wth + (size_t)widx*512*512;
    const unsigned short* Bl = g_wtl + (size_t)widx*512*512;

    int n0   = blockIdx.x * 64;
    int row0 = blockIdx.y * 128;

    float acc[2][4][4];
    #pragma unroll
    for (int mi = 0; mi < 2; mi++)
        #pragma unroll
        for (int ni = 0; ni < 4; ni++)
            #pragma unroll
            for (int c = 0; c < 4; c++) acc[mi][ni][c] = 0.f;

    auto issue_chunk = [&](int kb, uint32_t bufo) {
        int kbase = kb * 64;
        #pragma unroll
        for (int i = 0; i < 8; i++) {
            int idx = i*256 + tid;
            int a = idx >> 10;
            int rem = idx & 1023;
            int row = rem >> 3, q8 = rem & 7;
            const unsigned short* srcp = a ? Al : Ah;
            CP_ASYNC16(sbase + bufo + (a ? GM_AL : GM_AH) + row*144 + q8*16,
                       &srcp[(size_t)(row0+row)*512 + kbase + q8*8]);
        }
        #pragma unroll
        for (int i = 0; i < 4; i++) {
            int idx = i*256 + tid;
            int a = idx >> 9;
            int rem = idx & 511;
            int row = rem >> 3, q8 = rem & 7;
            const unsigned short* srcp = a ? Bl : Bh;
            CP_ASYNC16(sbase + bufo + (a ? GM_BL : GM_BH) + row*144 + q8*16,
                       &srcp[(size_t)(n0+row)*512 + kbase + q8*8]);
        }
        CP_COMMIT();
    };

    issue_chunk(0, 0);

    for (int kb = 0; kb < 8; kb++) {
        uint32_t bufo = (kb & 1) ? GM_BUF : 0;
        CP_WAIT0();
        __syncthreads();
        if (kb + 1 < 8)
            issue_chunk(kb + 1, ((kb + 1) & 1) ? GM_BUF : 0);

        #pragma unroll
        for (int ks = 0; ks < 4; ks++) {
            uint32_t a_hi[2][4], a_lo[2][4], b_hi[8], b_lo[8];
            #pragma unroll
            for (int mi = 0; mi < 2; mi++) {
                int row = wm*32 + mi*16 + (lane & 15);
                int kcol = ks*16 + ((lane >> 4) << 3);
                uint32_t off = bufo + (uint32_t)(row*144 + kcol*2);
                ldsm_x4(a_hi[mi][0], a_hi[mi][1], a_hi[mi][2], a_hi[mi][3],
                        sbase + GM_AH + off);
                ldsm_x4(a_lo[mi][0], a_lo[mi][1], a_lo[mi][2], a_lo[mi][3],
                        sbase + GM_AL + off);
            }
            #pragma unroll
            for (int g = 0; g < 2; g++) {
                int rr = lane & 7;
                int hk = (lane >> 3) & 1;
                int hn = (lane >> 4) & 1;
                int nrow = wn*32 + g*16 + hn*8 + rr;
                int kcol = ks*16 + hk*8;
                uint32_t off = bufo + (uint32_t)(nrow*144 + kcol*2);
                ldsm_x4(b_hi[g*4+0], b_hi[g*4+1], b_hi[g*4+2], b_hi[g*4+3],
                        sbase + GM_BH + off);
                ldsm_x4(b_lo[g*4+0], b_lo[g*4+1], b_lo[g*4+2], b_lo[g*4+3],
                        sbase + GM_BL + off);
            }
            #pragma unroll
            for (int mi = 0; mi < 2; mi++)
                #pragma unroll
                for (int ni = 0; ni < 4; ni++)
                    mma_f16(acc[mi][ni], a_hi[mi], &b_hi[ni*2]);
            #pragma unroll
            for (int mi = 0; mi < 2; mi++)
                #pragma unroll
                for (int ni = 0; ni < 4; ni++)
                    mma_f16(acc[mi][ni], a_lo[mi], &b_hi[ni*2]);
            if (mode < 3) {
                #pragma unroll
                for (int mi = 0; mi < 2; mi++)
                    #pragma unroll
                    for (int ni = 0; ni < 4; ni++)
                        mma_f16(acc[mi][ni], a_hi[mi], &b_lo[ni*2]);
            }
        }
    }

    float scale = (mode == 0) ? 0.125f * LOG2E_F : 1.f;
    #pragma unroll
    for (int mi = 0; mi < 2; mi++) {
        #pragma unroll
        for (int ni = 0; ni < 4; ni++) {
            int nl = wn*32 + ni*8 + (lane & 3)*2;
            float b0 = bias[n0 + nl], b1 = bias[n0 + nl + 1];
            #pragma unroll
            for (int half = 0; half < 2; half++) {
                int m = row0 + wm*32 + mi*16 + (lane >> 2) + half*8;
                float ox = (acc[mi][ni][half*2+0] + b0) * scale;
                float oy = (acc[mi][ni][half*2+1] + b1) * scale;
                if (mode < 3) {
                    int enc = m >> 12, b = (m >> 10) & 3, l = m & 1023;
                    int h = n0 >> 6;
                    size_t idx = ((((size_t)(enc*B_ + b))*H_ + h)*L_ + l)*HD_ + nl;
                    if (mode == 0) {
                        uint32_t hi, lo; split2(ox, oy, hi, lo);
                        *(uint32_t*)&g_qh[idx] = hi;
                        *(uint32_t*)&g_ql[idx] = lo;
                    } else if (mode == 1) {
                        uint32_t hi, lo; split2(ox, oy, hi, lo);
                        *(uint32_t*)&g_kh[idx] = hi;
                        *(uint32_t*)&g_kl[idx] = lo;
                    } else {
                        *(uint32_t*)&g_vh[idx] = pack2h(ox, oy);
                    }
                } else {
                    float2 o; o.x = ox; o.y = oy;
                    *(float2*)&outp[(size_t)m*D_ + nl + n0] = o;
                }
            }
        }
    }
}

// ===========================================================================
// Flash attention: QK 3-term, PV 2-term (V single fp16).
//   grid (16 qtiles, 32 b*h, 2 dirs), 128 threads (4 warps).
// KV stage: KH 0, KL 9216, VH 18432 -> 27648/stage, 2 stages.
// Q at 55296: QH + QL (9216 each). Total 73728.
// ===========================================================================
#define AT_BUF  27648
#define AT_KH   0
#define AT_KL   9216
#define AT_VH   18432
#define AT_Q    55296
#define AT_SMEM 73728

__global__ __launch_bounds__(128) void attn_mma_kernel()
{
    extern __shared__ __align__(16) unsigned char smem[];
    uint32_t sbase = smem_u32(smem);

    int tid = threadIdx.x;
    int wid = tid >> 5, lane = tid & 31;
    int r = lane >> 2, cq = lane & 3;

    int qt = blockIdx.x, bh = blockIdx.y, dir = blockIdx.z;
    int b = bh >> 3, h = bh & 7;
    int enc_q = dir, enc_kv = 1 - dir;

    size_t qoff  = ((size_t)((enc_q *B_ + b)*H_ + h))*L_*HD_;
    size_t kvoff = ((size_t)((enc_kv*B_ + b)*H_ + h))*L_*HD_;
    const unsigned short* Qh = g_qh + qoff;
    const unsigned short* Ql = g_ql + qoff;
    const unsigned short* Kh = g_kh + kvoff;
    const unsigned short* Kl = g_kl + kvoff;
    const unsigned short* Vh = g_vh + kvoff;
    const float* mb = g_mb + ((size_t)dir*B_ + b)*L_*L_;
    int q0 = qt * 64;

    // ---- Q cp.async: 2 arrays x 512 uint4 / 128 thr = 8 iters ----
    #pragma unroll
    for (int i = 0; i < 8; i++) {
        int idx = i*128 + tid;
        int a = idx >> 9;
        int rem = idx & 511;
        int row = rem >> 3, q8 = rem & 7;
        const unsigned short* srcp = a ? Ql : Qh;
        CP_ASYNC16(sbase + AT_Q + (a ? 9216 : 0) + row*144 + q8*16,
                   &srcp[(size_t)(q0+row)*HD_ + q8*8]);
    }
    CP_COMMIT();
    CP_WAIT0();
    __syncthreads();

    auto issue_kv = [&](int t, uint32_t bufo) {
        int k0 = t * 64;
        // 3 arrays x 512 uint4 = 1536 / 128 thr = 12 iters
        #pragma unroll
        for (int i = 0; i < 12; i++) {
            int idx = i*128 + tid;
            int a = idx >> 9;                  // 0=KH 1=KL 2=VH
            int rem = idx & 511;
            int row = rem >> 3, q8 = rem & 7;
            const unsigned short* srcp = (a == 0) ? Kh : (a == 1) ? Kl : Vh;
            int dsto = (a == 0) ? AT_KH : (a == 1) ? AT_KL : AT_VH;
            CP_ASYNC16(sbase + bufo + dsto + row*144 + q8*16,
                       &srcp[(size_t)(k0+row)*HD_ + q8*8]);
        }
        CP_COMMIT();
    };

    issue_kv(0, 0);

    // ---- Q A-fragments resident in regs ----
    uint32_t aq_h[4][4], aq_l[4][4];
    #pragma unroll
    for (int ks = 0; ks < 4; ks++) {
        int row = wid*16 + (lane & 15);
        int kcol = ks*16 + ((lane >> 4) << 3);
        uint32_t off = (uint32_t)(row*144 + kcol*2);
        ldsm_x4(aq_h[ks][0], aq_h[ks][1], aq_h[ks][2], aq_h[ks][3],
                sbase + AT_Q + off);
        ldsm_x4(aq_l[ks][0], aq_l[ks][1], aq_l[ks][2], aq_l[ks][3],
                sbase + AT_Q + 9216 + off);
    }

    float o_acc[8][4];
    #pragma unroll
    for (int nt = 0; nt < 8; nt++)
        #pragma unroll
        for (int c = 0; c < 4; c++) o_acc[nt][c] = 0.f;
    float m0r = -3.0e38f, m1r = -3.0e38f, l0r = 0.f, l1r = 0.f;

    int qg0 = q0 + wid*16 + r;
    int qg1 = qg0 + 8;
    const float* mb0 = mb + (size_t)qg0*L_ + cq*2;
    const float* mb1 = mb + (size_t)qg1*L_ + cq*2;

    for (int t = 0; t < 16; t++) {
        int k0 = t * 64;
        uint32_t bufo = (t & 1) ? AT_BUF : 0;
        CP_WAIT0();
        __syncthreads();
        if (t + 1 < 16)
            issue_kv(t + 1, ((t + 1) & 1) ? AT_BUF : 0);

        float2 mbv0[8], mbv1[8];
        #pragma unroll
        for (int nt = 0; nt < 8; nt++) {
            int cc = k0 + nt*8;
            mbv0[nt] = *(const float2*)&mb0[cc];
            mbv1[nt] = *(const float2*)&mb1[cc];
        }

        // ---- S = Q K^T (3-term) ----
        float s_acc[8][4];
        #pragma unroll
        for (int nt = 0; nt < 8; nt++)
            #pragma unroll
            for (int c = 0; c < 4; c++) s_acc[nt][c] = 0.f;

        #pragma unroll
        for (int ks = 0; ks < 4; ks++) {
            #pragma unroll
            for (int g = 0; g < 4; g++) {
                uint32_t bk_h[4], bk_l[4];
                int rr = lane & 7;
                int hk = (lane >> 3) & 1;
                int hn = (lane >> 4) & 1;
                int nrow = g*16 + hn*8 + rr;
                int kcol = ks*16 + hk*8;
                uint32_t off = bufo + (uint32_t)(nrow*144 + kcol*2);
                ldsm_x4(bk_h[0], bk_h[1], bk_h[2], bk_h[3], sbase + AT_KH + off);
                ldsm_x4(bk_l[0], bk_l[1], bk_l[2], bk_l[3], sbase + AT_KL + off);
                int n0t = g*2, n1t = g*2 + 1;
                mma_f16(s_acc[n0t], aq_h[ks], &bk_h[0]);
                mma_f16(s_acc[n1t], aq_h[ks], &bk_h[2]);
                mma_f16(s_acc[n0t], aq_l[ks], &bk_h[0]);
                mma_f16(s_acc[n1t], aq_l[ks], &bk_h[2]);
                mma_f16(s_acc[n0t], aq_h[ks], &bk_l[0]);
                mma_f16(s_acc[n1t], aq_h[ks], &bk_l[2]);
            }
        }

        // ---- additive mask+bias (log2 domain) ----
        #pragma unroll
        for (int nt = 0; nt < 8; nt++) {
            s_acc[nt][0] += mbv0[nt].x;
            s_acc[nt][1] += mbv0[nt].y;
            s_acc[nt][2] += mbv1[nt].x;
            s_acc[nt][3] += mbv1[nt].y;
        }

        // ---- online softmax (base-2) ----
        float mx0 = -3.0e38f, mx1 = -3.0e38f;
        #pragma unroll
        for (int nt = 0; nt < 8; nt++) {
            mx0 = fmaxf(mx0, fmaxf(s_acc[nt][0], s_acc[nt][1]));
            mx1 = fmaxf(mx1, fmaxf(s_acc[nt][2], s_acc[nt][3]));
        }
        mx0 = fmaxf(mx0, __shfl_xor_sync(0xffffffffu, mx0, 1));
        mx0 = fmaxf(mx0, __shfl_xor_sync(0xffffffffu, mx0, 2));
        mx1 = fmaxf(mx1, __shfl_xor_sync(0xffffffffu, mx1, 1));
        mx1 = fmaxf(mx1, __shfl_xor_sync(0xffffffffu, mx1, 2));

        float mn0 = fmaxf(m0r, mx0);
        float mn1 = fmaxf(m1r, mx1);
        float c0 = ex2f(m0r - mn0);
        float c1 = ex2f(m1r - mn1);
        m0r = mn0; m1r = mn1;

        float rs0 = 0.f, rs1 = 0.f;
        #pragma unroll
        for (int nt = 0; nt < 8; nt++) {
            s_acc[nt][0] = ex2f(s_acc[nt][0] - m0r); rs0 += s_acc[nt][0];
            s_acc[nt][1] = ex2f(s_acc[nt][1] - m0r); rs0 += s_acc[nt][1];
            s_acc[nt][2] = ex2f(s_acc[nt][2] - m1r); rs1 += s_acc[nt][2];
            s_acc[nt][3] = ex2f(s_acc[nt][3] - m1r); rs1 += s_acc[nt][3];
        }
        rs0 += __shfl_xor_sync(0xffffffffu, rs0, 1);
        rs0 += __shfl_xor_sync(0xffffffffu, rs0, 2);
        rs1 += __shfl_xor_sync(0xffffffffu, rs1, 1);
        rs1 += __shfl_xor_sync(0xffffffffu, rs1, 2);
        l0r = l0r*c0 + rs0;
        l1r = l1r*c1 + rs1;

        #pragma unroll
        for (int nt = 0; nt < 8; nt++) {
            o_acc[nt][0] *= c0; o_acc[nt][1] *= c0;
            o_acc[nt][2] *= c1; o_acc[nt][3] *= c1;
        }

        // ---- O += P V (2-term: P hi/lo x V single) ----
        #pragma unroll
        for (int ks = 0; ks < 4; ks++) {
            int t0 = 2*ks, t1 = 2*ks + 1;
            uint32_t ap_h[4], ap_l[4];
            split2(s_acc[t0][0], s_acc[t0][1], ap_h[0], ap_l[0]);
            split2(s_acc[t0][2], s_acc[t0][3], ap_h[1], ap_l[1]);
            split2(s_acc[t1][0], s_acc[t1][1], ap_h[2], ap_l[2]);
            split2(s_acc[t1][2], s_acc[t1][3], ap_h[3], ap_l[3]);
            #pragma unroll
            for (int g = 0; g < 4; g++) {
                uint32_t bv[4];
                int kk  = ks*16 + ((lane >> 3) & 1)*8 + (lane & 7);
                int hdo = g*16 + ((lane >> 4) & 1)*8;
                uint32_t off = bufo + (uint32_t)(kk*144 + hdo*2);
                ldsm_x4_t(bv[0], bv[1], bv[2], bv[3], sbase + AT_VH + off);
                int n0t = g*2, n1t = g*2 + 1;
                mma_f16(o_acc[n0t], ap_h, &bv[0]);
                mma_f16(o_acc[n1t], ap_h, &bv[2]);
                mma_f16(o_acc[n0t], ap_l, &bv[0]);
                mma_f16(o_acc[n1t], ap_l, &bv[2]);
            }
        }
    }

    // ---- finalize: ctx = O/l as fp16 hi/lo ----
    float inv0 = 1.f / l0r;
    float inv1 = 1.f / l1r;
    size_t base0 = ((size_t)(enc_q*B_ + b)*L_ + qg0)*D_ + h*64 + cq*2;
    size_t base1 = ((size_t)(enc_q*B_ + b)*L_ + qg1)*D_ + h*64 + cq*2;
    #pragma unroll
    for (int nt = 0; nt < 8; nt++) {
        uint32_t hi0, lo0, hi1, lo1;
        split2(o_acc[nt][0]*inv0, o_acc[nt][1]*inv0, hi0, lo0);
        split2(o_acc[nt][2]*inv1, o_acc[nt][3]*inv1, hi1, lo1);
        *(uint32_t*)&g_ch[base0 + nt*8] = hi0;
        *(uint32_t*)&g_cl[base0 + nt*8] = lo0;
        *(uint32_t*)&g_ch[base1 + nt*8] = hi1;
        *(uint32_t*)&g_cl[base1 + nt*8] = lo1;
    }
}

// ---------------------------------------------------------------------------
extern "C" void kernel_launch(void* const* d_in, const int* in_sizes, int n_in,
                              void* d_out, int out_size)
{
    const float* u_enc     = (const float*)d_in[0];
    const float* e_enc     = (const float*)d_in[1];
    const float* logit_bpp = (const float*)d_in[2];
    const void*  ue_mask   = d_in[3];
    const void*  eu_mask   = d_in[4];
    const float* wq_k = (const float*)d_in[5];
    const float* wq_b = (const float*)d_in[6];
    const float* wk_k = (const float*)d_in[7];
    const float* wk_b = (const float*)d_in[8];
    const float* wv_k = (const float*)d_in[9];
    const float* wv_b = (const float*)d_in[10];
    const float* wo_k = (const float*)d_in[11];
    const float* wo_b = (const float*)d_in[12];
    const float* bpp_w = (const float*)d_in[13];
    const float* bpp_b = (const float*)d_in[14];
    float* out = (float*)d_out;

    cudaFuncSetAttribute((const void*)attn_mma_kernel,
                         cudaFuncAttributeMaxDynamicSharedMemorySize, AT_SMEM);
    cudaFuncSetAttribute((const void*)gemm_mma_kernel,
                         cudaFuncAttributeMaxDynamicSharedMemorySize, GM_SMEM);

    // 0) mask dtype detection
    mask_detect_kernel<<<1, 256>>>((const unsigned int*)ue_mask);
    // 1) fused mask+bias (bpp computed inline, log2e-scaled)
    maskbias_kernel<<<dim3(32, 32, 2), dim3(32, 8)>>>(logit_bpp, bpp_w, bpp_b,
                                                      ue_mask, eu_mask);
    // 2) one-time operand splits (fp16)
    enc_split_kernel<<<dim3(1024, 1, 2), 256>>>(u_enc, e_enc);
    wt_split_kernel<<<dim3(16, 16, 4), dim3(32, 8)>>>(wq_k, wk_k, wv_k, wo_k);
    // 3) fused QKV projections (3-term; q scaled by 0.125*log2e)
    gemm_mma_kernel<<<dim3(8, 64, 3), 256, GM_SMEM>>>(wq_b, wk_b, wv_b, wo_b,
                                                      nullptr, 0);
    // 4) fused attention (QK 3-term, PV 2-term)
    attn_mma_kernel<<<dim3(16, 32, 2), 128, AT_SMEM>>>();
    // 5) output projection (2-term) -> d_out
    gemm_mma_kernel<<<dim3(8, 64, 1), 256, GM_SMEM>>>(wq_b, wk_b, wv_b, wo_b,
                                                      out, 3);
}

// round 11
// speedup vs baseline: 1.4931x; 1.1400x over previous
#include <cuda_runtime.h>
#include <cuda_fp16.h>
#include <math.h>
#include <float.h>
#include <stdint.h>
#include <string.h>

#define B_  4
#define L_  1024
#define D_  512
#define H_  8
#define HD_ 64
#define PROJ_ELEMS (2*B_*H_*L_*HD_)   /* 4,194,304 */
#define MASK_ELEMS ((size_t)B_*L_*L_) /* 4,194,304 */
#define ENC_ELEMS  (8192*512)
#define LOG2E_F 1.4426950408889634f

// producer-split fp16 storage
__device__ unsigned short g_ah[ENC_ELEMS], g_al[ENC_ELEMS];      // [u;e] inputs
__device__ unsigned short g_wth[4*512*512], g_wtl[4*512*512];    // W^T, n-major
__device__ unsigned short g_qh[PROJ_ELEMS], g_ql[PROJ_ELEMS];    // Q hi/lo
__device__ unsigned short g_kh[PROJ_ELEMS];                      // K single fp16
__device__ unsigned short g_vh[PROJ_ELEMS];                      // V single fp16
__device__ unsigned short g_ch[PROJ_ELEMS], g_cl[PROJ_ELEMS];    // ctx hi/lo
__device__ unsigned short g_mb[2*B_*L_*L_];  // fp16 (bias*log2e) | -30000 masked
__device__ int g_mtype;

// ===========================================================================
// helpers
// ===========================================================================
__device__ __forceinline__ uint32_t smem_u32(const void* p) {
    uint32_t a;
    asm("{ .reg .u64 t; cvta.to.shared.u64 t, %1; cvt.u32.u64 %0, t; }"
        : "=r"(a) : "l"(p));
    return a;
}
#define CP_ASYNC16(saddr, gptr) \
    asm volatile("cp.async.ca.shared.global [%0], [%1], 16;" \
                 :: "r"(saddr), "l"(gptr))
#define CP_COMMIT() asm volatile("cp.async.commit_group;" ::: "memory")
#define CP_WAIT0()  asm volatile("cp.async.wait_group 0;" ::: "memory")

__device__ __forceinline__ float ex2f(float x) {
    float r;
    asm("ex2.approx.f32 %0, %1;" : "=f"(r) : "f"(x));
    return r;
}
__device__ __forceinline__ void ldsm_x4(uint32_t& r0, uint32_t& r1,
                                        uint32_t& r2, uint32_t& r3,
                                        uint32_t addr) {
    asm volatile("ldmatrix.sync.aligned.m8n8.x4.shared.b16 {%0,%1,%2,%3}, [%4];"
                 : "=r"(r0), "=r"(r1), "=r"(r2), "=r"(r3) : "r"(addr));
}
__device__ __forceinline__ void ldsm_x4_t(uint32_t& r0, uint32_t& r1,
                                          uint32_t& r2, uint32_t& r3,
                                          uint32_t addr) {
    asm volatile("ldmatrix.sync.aligned.m8n8.x4.trans.shared.b16 {%0,%1,%2,%3}, [%4];"
                 : "=r"(r0), "=r"(r1), "=r"(r2), "=r"(r3) : "r"(addr));
}
__device__ __forceinline__ void mma_f16(float* c, const uint32_t* a,
                                        const uint32_t* b) {
    asm volatile("mma.sync.aligned.m16n8k16.row.col.f32.f16.f16.f32 "
                 "{%0,%1,%2,%3}, {%4,%5,%6,%7}, {%8,%9}, {%0,%1,%2,%3};"
                 : "+f"(c[0]), "+f"(c[1]), "+f"(c[2]), "+f"(c[3])
                 : "r"(a[0]), "r"(a[1]), "r"(a[2]), "r"(a[3]),
                   "r"(b[0]), "r"(b[1]));
}
__device__ __forceinline__ unsigned short f2h_bits(float x) {
    __half h = __float2half_rn(x);
    unsigned short u; memcpy(&u, &h, 2); return u;
}
__device__ __forceinline__ float hbits2f(unsigned short u) {
    __half h; memcpy(&h, &u, 2); return __half2float(h);
}
__device__ __forceinline__ void split2(float x, float y, uint32_t& hi, uint32_t& lo) {
    unsigned short hx = f2h_bits(x), hy = f2h_bits(y);
    unsigned short lx = f2h_bits(x - hbits2f(hx));
    unsigned short ly = f2h_bits(y - hbits2f(hy));
    hi = (uint32_t)hx | ((uint32_t)hy << 16);
    lo = (uint32_t)lx | ((uint32_t)ly << 16);
}
__device__ __forceinline__ uint32_t pack2h(float x, float y) {
    return (uint32_t)f2h_bits(x) | ((uint32_t)f2h_bits(y) << 16);
}
__device__ __forceinline__ float2 h2unpack(uint32_t w) {
    __half2 h; memcpy(&h, &w, 4);
    return __half22float2(h);
}

// ===========================================================================
// Mask dtype detection
// ===========================================================================
__global__ void mask_detect_kernel(const unsigned int* __restrict__ m)
{
    __shared__ int viol[3];
    if (threadIdx.x < 3) viol[threadIdx.x] = 0;
    __syncthreads();
    int v0 = 0, v1 = 0, v2 = 0;
    for (int i = threadIdx.x; i < 16384; i += 256) {
        unsigned w = m[i];
        if (w > 1u) v0 = 1;
        if (w != 0u && w != 0x3F800000u) v1 = 1;
        if (w != 0u && w != 0x3F800000u && w != 0x00003F80u && w != 0x3F803F80u) v2 = 1;
    }
    if (v0) atomicOr(&viol[0], 1);
    if (v1) atomicOr(&viol[1], 1);
    if (v2) atomicOr(&viol[2], 1);
    __syncthreads();
    if (threadIdx.x == 0) {
        int t;
        if      (!viol[0]) t = 1;
        else if (!viol[1]) t = 2;
        else if (!viol[2]) t = 3;
        else               t = 0;
        g_mtype = t;
    }
}

// ===========================================================================
// fused maskbias (fp16): g_mb = mask ? (w*lb(+T)+b)*log2e : -30000
// grid (32,32,2) block (32,8); dir1 transposes lb through smem.
// ===========================================================================
__global__ __launch_bounds__(256) void maskbias_kernel(
    const float* __restrict__ lb,
    const float* __restrict__ wp, const float* __restrict__ bp,
    const void* __restrict__ ue, const void* __restrict__ eu)
{
    __shared__ float s[32][33];
    int tx = threadIdx.x, ty = threadIdx.y;
    int dir = blockIdx.z;
    int mt = g_mtype;
    float w = wp[0] * LOG2E_F, bb = bp[0] * LOG2E_F;
    int k0 = blockIdx.x*32, q0 = blockIdx.y*32;
    const void* msk = dir ? eu : ue;
    unsigned short* dst = g_mb + (size_t)dir * MASK_ELEMS;

    if (dir == 1) {
        #pragma unroll
        for (int i = ty; i < 32; i += 8)
            s[i][tx] = lb[(size_t)(k0+i)*L_ + q0 + tx];
        __syncthreads();
    }

    #pragma unroll
    for (int i = ty; i < 32; i += 8) {
        float bias;
        if (dir == 0) bias = fmaf(w, lb[(size_t)(q0+i)*L_ + k0 + tx], bb);
        else          bias = fmaf(w, s[tx][i], bb);
        unsigned short bh = f2h_bits(bias);
        unsigned short mk = f2h_bits(-30000.0f);
        size_t rowoff = (size_t)(q0+i)*L_ + k0 + tx;
        #pragma unroll
        for (int b = 0; b < B_; b++) {
            size_t idx = ((size_t)b << 20) + rowoff;
            bool mv;
            if      (mt == 1) mv = ((const int*)msk)[idx] != 0;
            else if (mt == 2) mv = ((const float*)msk)[idx] != 0.f;
            else if (mt == 3) mv = ((const unsigned short*)msk)[idx] != 0;
            else              mv = ((const unsigned char*)msk)[idx] != 0;
            dst[idx] = mv ? bh : mk;
        }
    }
}

// ===========================================================================
// enc split (fp16 hi/lo)
// ===========================================================================
__global__ __launch_bounds__(256) void enc_split_kernel(
    const float* __restrict__ u, const float* __restrict__ e)
{
    const float* src = blockIdx.z ? e : u;
    size_t base4 = (size_t)blockIdx.z * (4096*512/4);
    size_t stride = (size_t)gridDim.x * blockDim.x;
    for (size_t i4 = (size_t)blockIdx.x*blockDim.x + threadIdx.x;
         i4 < 4096*512/4; i4 += stride) {
        float4 v = ((const float4*)src)[i4];
        uint32_t h01, l01, h23, l23;
        split2(v.x, v.y, h01, l01);
        split2(v.z, v.w, h23, l23);
        ((uint2*)g_ah)[base4 + i4] = make_uint2(h01, h23);
        ((uint2*)g_al)[base4 + i4] = make_uint2(l01, l23);
    }
}

// ===========================================================================
// weight transpose+split (fp16 hi/lo)
// ===========================================================================
__global__ __launch_bounds__(256) void wt_split_kernel(
    const float* __restrict__ wq, const float* __restrict__ wk,
    const float* __restrict__ wv, const float* __restrict__ wo)
{
    const float* src = (blockIdx.z == 0) ? wq : (blockIdx.z == 1) ? wk
                     : (blockIdx.z == 2) ? wv : wo;
    __shared__ float t[32][33];
    int tx = threadIdx.x, ty = threadIdx.y;
    int x  = blockIdx.x*32 + tx;
    int y0 = blockIdx.y*32;
    #pragma unroll
    for (int i = ty; i < 32; i += 8)
        t[i][tx] = src[(size_t)(y0+i)*512 + x];
    __syncthreads();
    size_t base = (size_t)blockIdx.z * 512*512;
    int ko = y0 + tx;
    #pragma unroll
    for (int i = ty; i < 32; i += 8) {
        float v = t[tx][i];
        unsigned short h = f2h_bits(v);
        unsigned short l = f2h_bits(v - hbits2f(h));
        size_t idx = base + (size_t)(blockIdx.x*32+i)*512 + ko;
        g_wth[idx] = h;
        g_wtl[idx] = l;
    }
}

// ===========================================================================
// GEMM: 128M x 64N, K chunks 64, cp.async double-buffered.
//   mode 0 (Q): 3-term, out hi/lo. mode 1 (K)/2 (V): 2-term, out single.
//   mode 3 (out-proj): 2-term (ctx hi/lo x wo hi), fp32 out.
// B-lo only loaded for mode 0.
// ===========================================================================
#define GM_BUF  55296
#define GM_AH   0
#define GM_AL   18432
#define GM_BH   36864
#define GM_BL   46080
#define GM_SMEM 110592

__global__ __launch_bounds__(256) void gemm_mma_kernel(
    const float* __restrict__ bq, const float* __restrict__ bk,
    const float* __restrict__ bv, const float* __restrict__ bo,
    float* __restrict__ outp, int modebase)
{
    extern __shared__ __align__(16) unsigned char smem[];
    uint32_t sbase = smem_u32(smem);

    int tid = threadIdx.x;
    int wid = tid >> 5, lane = tid & 31;
    int wm = wid & 3, wn = wid >> 2;

    int mode = modebase + blockIdx.z;
    const float* bias;
    if      (mode == 0) bias = bq;
    else if (mode == 1) bias = bk;
    else if (mode == 2) bias = bv;
    else                bias = bo;

    const unsigned short* Ah = (mode < 3) ? g_ah : g_ch;
    const unsigned short* Al = (mode < 3) ? g_al : g_cl;
    int widx = (mode < 3) ? mode : 3;
    const unsigned short* Bh = g_wth + (size_t)widx*512*512;
    const unsigned short* Bl = g_wtl + (size_t)widx*512*512;
    bool three = (mode == 0);

    int n0   = blockIdx.x * 64;
    int row0 = blockIdx.y * 128;

    float acc[2][4][4];
    #pragma unroll
    for (int mi = 0; mi < 2; mi++)
        #pragma unroll
        for (int ni = 0; ni < 4; ni++)
            #pragma unroll
            for (int c = 0; c < 4; c++) acc[mi][ni][c] = 0.f;

    auto issue_chunk = [&](int kb, uint32_t bufo) {
        int kbase = kb * 64;
        #pragma unroll
        for (int i = 0; i < 8; i++) {
            int idx = i*256 + tid;
            int a = idx >> 10;
            int rem = idx & 1023;
            int row = rem >> 3, q8 = rem & 7;
            const unsigned short* srcp = a ? Al : Ah;
            CP_ASYNC16(sbase + bufo + (a ? GM_AL : GM_AH) + row*144 + q8*16,
                       &srcp[(size_t)(row0+row)*512 + kbase + q8*8]);
        }
        // B hi always (2 iters); B lo only for 3-term mode
        #pragma unroll
        for (int i = 0; i < 2; i++) {
            int idx = i*256 + tid;
            int row = idx >> 3, q8 = idx & 7;
            CP_ASYNC16(sbase + bufo + GM_BH + row*144 + q8*16,
                       &Bh[(size_t)(n0+row)*512 + kbase + q8*8]);
        }
        if (three) {
            #pragma unroll
            for (int i = 0; i < 2; i++) {
                int idx = i*256 + tid;
                int row = idx >> 3, q8 = idx & 7;
                CP_ASYNC16(sbase + bufo + GM_BL + row*144 + q8*16,
                           &Bl[(size_t)(n0+row)*512 + kbase + q8*8]);
            }
        }
        CP_COMMIT();
    };

    issue_chunk(0, 0);

    for (int kb = 0; kb < 8; kb++) {
        uint32_t bufo = (kb & 1) ? GM_BUF : 0;
        CP_WAIT0();
        __syncthreads();
        if (kb + 1 < 8)
            issue_chunk(kb + 1, ((kb + 1) & 1) ? GM_BUF : 0);

        #pragma unroll
        for (int ks = 0; ks < 4; ks++) {
            uint32_t a_hi[2][4], a_lo[2][4], b_hi[8], b_lo[8];
            #pragma unroll
            for (int mi = 0; mi < 2; mi++) {
                int row = wm*32 + mi*16 + (lane & 15);
                int kcol = ks*16 + ((lane >> 4) << 3);
                uint32_t off = bufo + (uint32_t)(row*144 + kcol*2);
                ldsm_x4(a_hi[mi][0], a_hi[mi][1], a_hi[mi][2], a_hi[mi][3],
                        sbase + GM_AH + off);
                ldsm_x4(a_lo[mi][0], a_lo[mi][1], a_lo[mi][2], a_lo[mi][3],
                        sbase + GM_AL + off);
            }
            #pragma unroll
            for (int g = 0; g < 2; g++) {
                int rr = lane & 7;
                int hk = (lane >> 3) & 1;
                int hn = (lane >> 4) & 1;
                int nrow = wn*32 + g*16 + hn*8 + rr;
                int kcol = ks*16 + hk*8;
                uint32_t off = bufo + (uint32_t)(nrow*144 + kcol*2);
                ldsm_x4(b_hi[g*4+0], b_hi[g*4+1], b_hi[g*4+2], b_hi[g*4+3],
                        sbase + GM_BH + off);
                if (three)
                    ldsm_x4(b_lo[g*4+0], b_lo[g*4+1], b_lo[g*4+2], b_lo[g*4+3],
                            sbase + GM_BL + off);
            }
            #pragma unroll
            for (int mi = 0; mi < 2; mi++)
                #pragma unroll
                for (int ni = 0; ni < 4; ni++)
                    mma_f16(acc[mi][ni], a_hi[mi], &b_hi[ni*2]);
            #pragma unroll
            for (int mi = 0; mi < 2; mi++)
                #pragma unroll
                for (int ni = 0; ni < 4; ni++)
                    mma_f16(acc[mi][ni], a_lo[mi], &b_hi[ni*2]);
            if (three) {
                #pragma unroll
                for (int mi = 0; mi < 2; mi++)
                    #pragma unroll
                    for (int ni = 0; ni < 4; ni++)
                        mma_f16(acc[mi][ni], a_hi[mi], &b_lo[ni*2]);
            }
        }
    }

    float scale = (mode == 0) ? 0.125f * LOG2E_F : 1.f;
    #pragma unroll
    for (int mi = 0; mi < 2; mi++) {
        #pragma unroll
        for (int ni = 0; ni < 4; ni++) {
            int nl = wn*32 + ni*8 + (lane & 3)*2;
            float b0 = bias[n0 + nl], b1 = bias[n0 + nl + 1];
            #pragma unroll
            for (int half = 0; half < 2; half++) {
                int m = row0 + wm*32 + mi*16 + (lane >> 2) + half*8;
                float ox = (acc[mi][ni][half*2+0] + b0) * scale;
                float oy = (acc[mi][ni][half*2+1] + b1) * scale;
                if (mode < 3) {
                    int enc = m >> 12, b = (m >> 10) & 3, l = m & 1023;
                    int h = n0 >> 6;
                    size_t idx = ((((size_t)(enc*B_ + b))*H_ + h)*L_ + l)*HD_ + nl;
                    if (mode == 0) {
                        uint32_t hi, lo; split2(ox, oy, hi, lo);
                        *(uint32_t*)&g_qh[idx] = hi;
                        *(uint32_t*)&g_ql[idx] = lo;
                    } else if (mode == 1) {
                        *(uint32_t*)&g_kh[idx] = pack2h(ox, oy);
                    } else {
                        *(uint32_t*)&g_vh[idx] = pack2h(ox, oy);
                    }
                } else {
                    float2 o; o.x = ox; o.y = oy;
                    *(float2*)&outp[(size_t)m*D_ + nl + n0] = o;
                }
            }
        }
    }
}

// ===========================================================================
// Flash attention: QK 2-term (Q hi/lo x K single), PV 2-term (P hi/lo x V).
//   grid (16 qtiles, 32 b*h, 2 dirs), 128 threads (4 warps).
// KV stage: KH 0, VH 9216 -> 18432/stage, 2 stages. Q at 36864 (QH+QL).
// ===========================================================================
#define AT_BUF  18432
#define AT_KH   0
#define AT_VH   9216
#define AT_Q    36864
#define AT_SMEM 55296

__global__ __launch_bounds__(128) void attn_mma_kernel()
{
    extern __shared__ __align__(16) unsigned char smem[];
    uint32_t sbase = smem_u32(smem);

    int tid = threadIdx.x;
    int wid = tid >> 5, lane = tid & 31;
    int r = lane >> 2, cq = lane & 3;

    int qt = blockIdx.x, bh = blockIdx.y, dir = blockIdx.z;
    int b = bh >> 3, h = bh & 7;
    int enc_q = dir, enc_kv = 1 - dir;

    size_t qoff  = ((size_t)((enc_q *B_ + b)*H_ + h))*L_*HD_;
    size_t kvoff = ((size_t)((enc_kv*B_ + b)*H_ + h))*L_*HD_;
    const unsigned short* Qh = g_qh + qoff;
    const unsigned short* Ql = g_ql + qoff;
    const unsigned short* Kh = g_kh + kvoff;
    const unsigned short* Vh = g_vh + kvoff;
    const unsigned short* mb = g_mb + ((size_t)dir*B_ + b)*L_*L_;
    int q0 = qt * 64;

    // ---- Q cp.async: 2 arrays x 512 uint4 / 128 thr = 8 iters ----
    #pragma unroll
    for (int i = 0; i < 8; i++) {
        int idx = i*128 + tid;
        int a = idx >> 9;
        int rem = idx & 511;
        int row = rem >> 3, q8 = rem & 7;
        const unsigned short* srcp = a ? Ql : Qh;
        CP_ASYNC16(sbase + AT_Q + (a ? 9216 : 0) + row*144 + q8*16,
                   &srcp[(size_t)(q0+row)*HD_ + q8*8]);
    }
    CP_COMMIT();
    CP_WAIT0();
    __syncthreads();

    auto issue_kv = [&](int t, uint32_t bufo) {
        int k0 = t * 64;
        // 2 arrays x 512 uint4 = 1024 / 128 thr = 8 iters
        #pragma unroll
        for (int i = 0; i < 8; i++) {
            int idx = i*128 + tid;
            int a = idx >> 9;                  // 0=KH 1=VH
            int rem = idx & 511;
            int row = rem >> 3, q8 = rem & 7;
            const unsigned short* srcp = a ? Vh : Kh;
            int dsto = a ? AT_VH : AT_KH;
            CP_ASYNC16(sbase + bufo + dsto + row*144 + q8*16,
                       &srcp[(size_t)(k0+row)*HD_ + q8*8]);
        }
        CP_COMMIT();
    };

    issue_kv(0, 0);

    // ---- Q A-fragments resident in regs ----
    uint32_t aq_h[4][4], aq_l[4][4];
    #pragma unroll
    for (int ks = 0; ks < 4; ks++) {
        int row = wid*16 + (lane & 15);
        int kcol = ks*16 + ((lane >> 4) << 3);
        uint32_t off = (uint32_t)(row*144 + kcol*2);
        ldsm_x4(aq_h[ks][0], aq_h[ks][1], aq_h[ks][2], aq_h[ks][3],
                sbase + AT_Q + off);
        ldsm_x4(aq_l[ks][0], aq_l[ks][1], aq_l[ks][2], aq_l[ks][3],
                sbase + AT_Q + 9216 + off);
    }

    float o_acc[8][4];
    #pragma unroll
    for (int nt = 0; nt < 8; nt++)
        #pragma unroll
        for (int c = 0; c < 4; c++) o_acc[nt][c] = 0.f;
    float m0r = -3.0e38f, m1r = -3.0e38f, l0r = 0.f, l1r = 0.f;

    int qg0 = q0 + wid*16 + r;
    int qg1 = qg0 + 8;
    const unsigned short* mb0 = mb + (size_t)qg0*L_ + cq*2;
    const unsigned short* mb1 = mb + (size_t)qg1*L_ + cq*2;

    for (int t = 0; t < 16; t++) {
        int k0 = t * 64;
        uint32_t bufo = (t & 1) ? AT_BUF : 0;
        CP_WAIT0();
        __syncthreads();
        if (t + 1 < 16)
            issue_kv(t + 1, ((t + 1) & 1) ? AT_BUF : 0);

        float2 mbv0[8], mbv1[8];
        #pragma unroll
        for (int nt = 0; nt < 8; nt++) {
            int cc = k0 + nt*8;
            mbv0[nt] = h2unpack(*(const uint32_t*)&mb0[cc]);
            mbv1[nt] = h2unpack(*(const uint32_t*)&mb1[cc]);
        }

        // ---- S = Q K^T (2-term: q hi/lo x k single) ----
        float s_acc[8][4];
        #pragma unroll
        for (int nt = 0; nt < 8; nt++)
            #pragma unroll
            for (int c = 0; c < 4; c++) s_acc[nt][c] = 0.f;

        #pragma unroll
        for (int ks = 0; ks < 4; ks++) {
            #pragma unroll
            for (int g = 0; g < 4; g++) {
                uint32_t bk[4];
                int rr = lane & 7;
                int hk = (lane >> 3) & 1;
                int hn = (lane >> 4) & 1;
                int nrow = g*16 + hn*8 + rr;
                int kcol = ks*16 + hk*8;
                uint32_t off = bufo + (uint32_t)(nrow*144 + kcol*2);
                ldsm_x4(bk[0], bk[1], bk[2], bk[3], sbase + AT_KH + off);
                int n0t = g*2, n1t = g*2 + 1;
                mma_f16(s_acc[n0t], aq_h[ks], &bk[0]);
                mma_f16(s_acc[n1t], aq_h[ks], &bk[2]);
                mma_f16(s_acc[n0t], aq_l[ks], &bk[0]);
                mma_f16(s_acc[n1t], aq_l[ks], &bk[2]);
            }
        }

        // ---- additive mask+bias (log2 domain) ----
        #pragma unroll
        for (int nt = 0; nt < 8; nt++) {
            s_acc[nt][0] += mbv0[nt].x;
            s_acc[nt][1] += mbv0[nt].y;
            s_acc[nt][2] += mbv1[nt].x;
            s_acc[nt][3] += mbv1[nt].y;
        }

        // ---- online softmax (base-2) ----
        float mx0 = -3.0e38f, mx1 = -3.0e38f;
        #pragma unroll
        for (int nt = 0; nt < 8; nt++) {
            mx0 = fmaxf(mx0, fmaxf(s_acc[nt][0], s_acc[nt][1]));
            mx1 = fmaxf(mx1, fmaxf(s_acc[nt][2], s_acc[nt][3]));
        }
        mx0 = fmaxf(mx0, __shfl_xor_sync(0xffffffffu, mx0, 1));
        mx0 = fmaxf(mx0, __shfl_xor_sync(0xffffffffu, mx0, 2));
        mx1 = fmaxf(mx1, __shfl_xor_sync(0xffffffffu, mx1, 1));
        mx1 = fmaxf(mx1, __shfl_xor_sync(0xffffffffu, mx1, 2));

        float mn0 = fmaxf(m0r, mx0);
        float mn1 = fmaxf(m1r, mx1);
        float c0 = ex2f(m0r - mn0);
        float c1 = ex2f(m1r - mn1);
        m0r = mn0; m1r = mn1;

        float rs0 = 0.f, rs1 = 0.f;
        #pragma unroll
        for (int nt = 0; nt < 8; nt++) {
            s_acc[nt][0] = ex2f(s_acc[nt][0] - m0r); rs0 += s_acc[nt][0];
            s_acc[nt][1] = ex2f(s_acc[nt][1] - m0r); rs0 += s_acc[nt][1];
            s_acc[nt][2] = ex2f(s_acc[nt][2] - m1r); rs1 += s_acc[nt][2];
            s_acc[nt][3] = ex2f(s_acc[nt][3] - m1r); rs1 += s_acc[nt][3];
        }
        rs0 += __shfl_xor_sync(0xffffffffu, rs0, 1);
        rs0 += __shfl_xor_sync(0xffffffffu, rs0, 2);
        rs1 += __shfl_xor_sync(0xffffffffu, rs1, 1);
        rs1 += __shfl_xor_sync(0xffffffffu, rs1, 2);
        l0r = l0r*c0 + rs0;
        l1r = l1r*c1 + rs1;

        #pragma unroll
        for (int nt = 0; nt < 8; nt++) {
            o_acc[nt][0] *= c0; o_acc[nt][1] *= c0;
            o_acc[nt][2] *= c1; o_acc[nt][3] *= c1;
        }

        // ---- O += P V (2-term: P hi/lo x V single) ----
        #pragma unroll
        for (int ks = 0; ks < 4; ks++) {
            int t0 = 2*ks, t1 = 2*ks + 1;
            uint32_t ap_h[4], ap_l[4];
            split2(s_acc[t0][0], s_acc[t0][1], ap_h[0], ap_l[0]);
            split2(s_acc[t0][2], s_acc[t0][3], ap_h[1], ap_l[1]);
            split2(s_acc[t1][0], s_acc[t1][1], ap_h[2], ap_l[2]);
            split2(s_acc[t1][2], s_acc[t1][3], ap_h[3], ap_l[3]);
            #pragma unroll
            for (int g = 0; g < 4; g++) {
                uint32_t bv[4];
                int kk  = ks*16 + ((lane >> 3) & 1)*8 + (lane & 7);
                int hdo = g*16 + ((lane >> 4) & 1)*8;
                uint32_t off = bufo + (uint32_t)(kk*144 + hdo*2);
                ldsm_x4_t(bv[0], bv[1], bv[2], bv[3], sbase + AT_VH + off);
                int n0t = g*2, n1t = g*2 + 1;
                mma_f16(o_acc[n0t], ap_h, &bv[0]);
                mma_f16(o_acc[n1t], ap_h, &bv[2]);
                mma_f16(o_acc[n0t], ap_l, &bv[0]);
                mma_f16(o_acc[n1t], ap_l, &bv[2]);
            }
        }
    }

    // ---- finalize: ctx = O/l as fp16 hi/lo ----
    float inv0 = 1.f / l0r;
    float inv1 = 1.f / l1r;
    size_t base0 = ((size_t)(enc_q*B_ + b)*L_ + qg0)*D_ + h*64 + cq*2;
    size_t base1 = ((size_t)(enc_q*B_ + b)*L_ + qg1)*D_ + h*64 + cq*2;
    #pragma unroll
    for (int nt = 0; nt < 8; nt++) {
        uint32_t hi0, lo0, hi1, lo1;
        split2(o_acc[nt][0]*inv0, o_acc[nt][1]*inv0, hi0, lo0);
        split2(o_acc[nt][2]*inv1, o_acc[nt][3]*inv1, hi1, lo1);
        *(uint32_t*)&g_ch[base0 + nt*8] = hi0;
        *(uint32_t*)&g_cl[base0 + nt*8] = lo0;
        *(uint32_t*)&g_ch[base1 + nt*8] = hi1;
        *(uint32_t*)&g_cl[base1 + nt*8] = lo1;
    }
}

// ---------------------------------------------------------------------------
extern "C" void kernel_launch(void* const* d_in, const int* in_sizes, int n_in,
                              void* d_out, int out_size)
{
    const float* u_enc     = (const float*)d_in[0];
    const float* e_enc     = (const float*)d_in[1];
    const float* logit_bpp = (const float*)d_in[2];
    const void*  ue_mask   = d_in[3];
    const void*  eu_mask   = d_in[4];
    const float* wq_k = (const float*)d_in[5];
    const float* wq_b = (const float*)d_in[6];
    const float* wk_k = (const float*)d_in[7];
    const float* wk_b = (const float*)d_in[8];
    const float* wv_k = (const float*)d_in[9];
    const float* wv_b = (const float*)d_in[10];
    const float* wo_k = (const float*)d_in[11];
    const float* wo_b = (const float*)d_in[12];
    const float* bpp_w = (const float*)d_in[13];
    const float* bpp_b = (const float*)d_in[14];
    float* out = (float*)d_out;

    cudaFuncSetAttribute((const void*)attn_mma_kernel,
                         cudaFuncAttributeMaxDynamicSharedMemorySize, AT_SMEM);
    cudaFuncSetAttribute((const void*)gemm_mma_kernel,
                         cudaFuncAttributeMaxDynamicSharedMemorySize, GM_SMEM);

    // 0) mask dtype detection
    mask_detect_kernel<<<1, 256>>>((const unsigned int*)ue_mask);
    // 1) fused mask+bias -> fp16 (log2e-scaled, masked = -30000)
    maskbias_kernel<<<dim3(32, 32, 2), dim3(32, 8)>>>(logit_bpp, bpp_w, bpp_b,
                                                      ue_mask, eu_mask);
    // 2) one-time operand splits (fp16)
    enc_split_kernel<<<dim3(1024, 1, 2), 256>>>(u_enc, e_enc);
    wt_split_kernel<<<dim3(16, 16, 4), dim3(32, 8)>>>(wq_k, wk_k, wv_k, wo_k);
    // 3) fused QKV projections (Q 3-term hi/lo; K,V 2-term single)
    gemm_mma_kernel<<<dim3(8, 64, 3), 256, GM_SMEM>>>(wq_b, wk_b, wv_b, wo_b,
                                                      nullptr, 0);
    // 4) fused attention (QK 2-term, PV 2-term)
    attn_mma_kernel<<<dim3(16, 32, 2), 128, AT_SMEM>>>();
    // 5) output projection (2-term) -> d_out
    gemm_mma_kernel<<<dim3(8, 64, 1), 256, GM_SMEM>>>(wq_b, wk_b, wv_b, wo_b,
                                                      out, 3);
}

// round 12
// speedup vs baseline: 1.5238x; 1.0205x over previous
#include <cuda_runtime.h>
#include <cuda_fp16.h>
#include <math.h>
#include <float.h>
#include <stdint.h>
#include <string.h>

#define B_  4
#define L_  1024
#define D_  512
#define H_  8
#define HD_ 64
#define PROJ_ELEMS (2*B_*H_*L_*HD_)   /* 4,194,304 */
#define MASK_ELEMS ((size_t)B_*L_*L_) /* 4,194,304 */
#define ENC_ELEMS  (8192*512)
#define LOG2E_F 1.4426950408889634f

// producer-split fp16 storage
__device__ unsigned short g_ah[ENC_ELEMS], g_al[ENC_ELEMS];      // [u;e] inputs
__device__ unsigned short g_wth[4*512*512], g_wtl[4*512*512];    // W^T, n-major
__device__ unsigned short g_qh[PROJ_ELEMS], g_ql[PROJ_ELEMS];    // Q hi/lo
__device__ unsigned short g_kh[PROJ_ELEMS];                      // K single fp16
__device__ unsigned short g_vh[PROJ_ELEMS];                      // V single fp16
__device__ unsigned short g_ch[PROJ_ELEMS], g_cl[PROJ_ELEMS];    // ctx hi/lo
__device__ unsigned short g_mb[2*B_*L_*L_];  // fp16 (bias*log2e) | -30000 masked
__device__ int g_mtype;

// ===========================================================================
// helpers
// ===========================================================================
__device__ __forceinline__ uint32_t smem_u32(const void* p) {
    uint32_t a;
    asm("{ .reg .u64 t; cvta.to.shared.u64 t, %1; cvt.u32.u64 %0, t; }"
        : "=r"(a) : "l"(p));
    return a;
}
#define CP_ASYNC16(saddr, gptr) \
    asm volatile("cp.async.ca.shared.global [%0], [%1], 16;" \
                 :: "r"(saddr), "l"(gptr))
#define CP_COMMIT() asm volatile("cp.async.commit_group;" ::: "memory")
#define CP_WAIT0()  asm volatile("cp.async.wait_group 0;" ::: "memory")

__device__ __forceinline__ float ex2f(float x) {
    float r;
    asm("ex2.approx.f32 %0, %1;" : "=f"(r) : "f"(x));
    return r;
}
__device__ __forceinline__ void ldsm_x4(uint32_t& r0, uint32_t& r1,
                                        uint32_t& r2, uint32_t& r3,
                                        uint32_t addr) {
    asm volatile("ldmatrix.sync.aligned.m8n8.x4.shared.b16 {%0,%1,%2,%3}, [%4];"
                 : "=r"(r0), "=r"(r1), "=r"(r2), "=r"(r3) : "r"(addr));
}
__device__ __forceinline__ void ldsm_x4_t(uint32_t& r0, uint32_t& r1,
                                          uint32_t& r2, uint32_t& r3,
                                          uint32_t addr) {
    asm volatile("ldmatrix.sync.aligned.m8n8.x4.trans.shared.b16 {%0,%1,%2,%3}, [%4];"
                 : "=r"(r0), "=r"(r1), "=r"(r2), "=r"(r3) : "r"(addr));
}
__device__ __forceinline__ void mma_f16(float* c, const uint32_t* a,
                                        const uint32_t* b) {
    asm volatile("mma.sync.aligned.m16n8k16.row.col.f32.f16.f16.f32 "
                 "{%0,%1,%2,%3}, {%4,%5,%6,%7}, {%8,%9}, {%0,%1,%2,%3};"
                 : "+f"(c[0]), "+f"(c[1]), "+f"(c[2]), "+f"(c[3])
                 : "r"(a[0]), "r"(a[1]), "r"(a[2]), "r"(a[3]),
                   "r"(b[0]), "r"(b[1]));
}
__device__ __forceinline__ unsigned short f2h_bits(float x) {
    __half h = __float2half_rn(x);
    unsigned short u; memcpy(&u, &h, 2); return u;
}
__device__ __forceinline__ float hbits2f(unsigned short u) {
    __half h; memcpy(&h, &u, 2); return __half2float(h);
}
__device__ __forceinline__ void split2(float x, float y, uint32_t& hi, uint32_t& lo) {
    unsigned short hx = f2h_bits(x), hy = f2h_bits(y);
    unsigned short lx = f2h_bits(x - hbits2f(hx));
    unsigned short ly = f2h_bits(y - hbits2f(hy));
    hi = (uint32_t)hx | ((uint32_t)hy << 16);
    lo = (uint32_t)lx | ((uint32_t)ly << 16);
}
__device__ __forceinline__ uint32_t pack2h(float x, float y) {
    return (uint32_t)f2h_bits(x) | ((uint32_t)f2h_bits(y) << 16);
}
__device__ __forceinline__ float2 h2unpack(uint32_t w) {
    __half2 h; memcpy(&h, &w, 4);
    return __half22float2(h);
}

// ===========================================================================
// Mask dtype detection
// ===========================================================================
__global__ void mask_detect_kernel(const unsigned int* __restrict__ m)
{
    __shared__ int viol[3];
    if (threadIdx.x < 3) viol[threadIdx.x] = 0;
    __syncthreads();
    int v0 = 0, v1 = 0, v2 = 0;
    for (int i = threadIdx.x; i < 16384; i += 256) {
        unsigned w = m[i];
        if (w > 1u) v0 = 1;
        if (w != 0u && w != 0x3F800000u) v1 = 1;
        if (w != 0u && w != 0x3F800000u && w != 0x00003F80u && w != 0x3F803F80u) v2 = 1;
    }
    if (v0) atomicOr(&viol[0], 1);
    if (v1) atomicOr(&viol[1], 1);
    if (v2) atomicOr(&viol[2], 1);
    __syncthreads();
    if (threadIdx.x == 0) {
        int t;
        if      (!viol[0]) t = 1;
        else if (!viol[1]) t = 2;
        else if (!viol[2]) t = 3;
        else               t = 0;
        g_mtype = t;
    }
}

// ===========================================================================
// Fused prep: blocks [0,2048) maskbias, [2048,4096) enc split, [4096,5120) wt.
// 256 threads each.
// ===========================================================================
__global__ __launch_bounds__(256) void prep_kernel(
    const float* __restrict__ lb,
    const float* __restrict__ wp, const float* __restrict__ bp,
    const void* __restrict__ ue, const void* __restrict__ eu,
    const float* __restrict__ u, const float* __restrict__ e,
    const float* __restrict__ wq, const float* __restrict__ wk,
    const float* __restrict__ wv, const float* __restrict__ wo)
{
    __shared__ float s[32][33];
    int bx = blockIdx.x;
    int tid = threadIdx.x;
    int tx = tid & 31, ty = tid >> 5;

    if (bx < 2048) {
        // ---- maskbias: dir = bx>>10, qy = (bx>>5)&31, kx = bx&31 ----
        int dir = bx >> 10;
        int q0 = ((bx >> 5) & 31) * 32;
        int k0 = (bx & 31) * 32;
        int mt = g_mtype;
        float w = wp[0] * LOG2E_F, bb = bp[0] * LOG2E_F;
        const void* msk = dir ? eu : ue;
        unsigned short* dst = g_mb + (size_t)dir * MASK_ELEMS;

        if (dir == 1) {
            #pragma unroll
            for (int i = ty; i < 32; i += 8)
                s[i][tx] = lb[(size_t)(k0+i)*L_ + q0 + tx];
            __syncthreads();
        }
        unsigned short mk = f2h_bits(-30000.0f);
        #pragma unroll
        for (int i = ty; i < 32; i += 8) {
            float bias;
            if (dir == 0) bias = fmaf(w, lb[(size_t)(q0+i)*L_ + k0 + tx], bb);
            else          bias = fmaf(w, s[tx][i], bb);
            unsigned short bh = f2h_bits(bias);
            size_t rowoff = (size_t)(q0+i)*L_ + k0 + tx;
            #pragma unroll
            for (int b = 0; b < B_; b++) {
                size_t idx = ((size_t)b << 20) + rowoff;
                bool mv;
                if      (mt == 1) mv = ((const int*)msk)[idx] != 0;
                else if (mt == 2) mv = ((const float*)msk)[idx] != 0.f;
                else if (mt == 3) mv = ((const unsigned short*)msk)[idx] != 0;
                else              mv = ((const unsigned char*)msk)[idx] != 0;
                dst[idx] = mv ? bh : mk;
            }
        }
    } else if (bx < 4096) {
        // ---- enc split: idx = bx-2048; z = idx>>10, blk = idx&1023 ----
        int idx = bx - 2048;
        int z = idx >> 10, blk = idx & 1023;
        const float* src = z ? e : u;
        size_t base4 = (size_t)z * (4096*512/4);
        size_t stride = 1024u * 256u;
        for (size_t i4 = (size_t)blk*256 + tid; i4 < 4096*512/4; i4 += stride) {
            float4 v = ((const float4*)src)[i4];
            uint32_t h01, l01, h23, l23;
            split2(v.x, v.y, h01, l01);
            split2(v.z, v.w, h23, l23);
            ((uint2*)g_ah)[base4 + i4] = make_uint2(h01, h23);
            ((uint2*)g_al)[base4 + i4] = make_uint2(l01, l23);
        }
    } else {
        // ---- wt split: idx = bx-4096; z = idx>>8, by=(idx>>4)&15, bxx=idx&15
        int idx = bx - 4096;
        int z = idx >> 8, by = (idx >> 4) & 15, bxx = idx & 15;
        const float* src = (z == 0) ? wq : (z == 1) ? wk : (z == 2) ? wv : wo;
        int x  = bxx*32 + tx;
        int y0 = by*32;
        #pragma unroll
        for (int i = ty; i < 32; i += 8)
            s[i][tx] = src[(size_t)(y0+i)*512 + x];
        __syncthreads();
        size_t base = (size_t)z * 512*512;
        int ko = y0 + tx;
        #pragma unroll
        for (int i = ty; i < 32; i += 8) {
            float v = s[tx][i];
            unsigned short h = f2h_bits(v);
            unsigned short l = f2h_bits(v - hbits2f(h));
            size_t widx = base + (size_t)(bxx*32+i)*512 + ko;
            g_wth[widx] = h;
            g_wtl[widx] = l;
        }
    }
}

// ===========================================================================
// GEMM: 128M x 64N, K chunks 64, cp.async double-buffered.
//   mode 0 (Q): 3-term, out hi/lo. mode 1 (K)/2 (V): 2-term, out single.
//   mode 3 (out-proj): 2-term (ctx hi/lo x wo hi), fp32 out.
// ===========================================================================
#define GM_BUF  55296
#define GM_AH   0
#define GM_AL   18432
#define GM_BH   36864
#define GM_BL   46080
#define GM_SMEM 110592

__global__ __launch_bounds__(256) void gemm_mma_kernel(
    const float* __restrict__ bq, const float* __restrict__ bk,
    const float* __restrict__ bv, const float* __restrict__ bo,
    float* __restrict__ outp, int modebase)
{
    extern __shared__ __align__(16) unsigned char smem[];
    uint32_t sbase = smem_u32(smem);

    int tid = threadIdx.x;
    int wid = tid >> 5, lane = tid & 31;
    int wm = wid & 3, wn = wid >> 2;

    int mode = modebase + blockIdx.z;
    const float* bias;
    if      (mode == 0) bias = bq;
    else if (mode == 1) bias = bk;
    else if (mode == 2) bias = bv;
    else                bias = bo;

    const unsigned short* Ah = (mode < 3) ? g_ah : g_ch;
    const unsigned short* Al = (mode < 3) ? g_al : g_cl;
    int widx = (mode < 3) ? mode : 3;
    const unsigned short* Bh = g_wth + (size_t)widx*512*512;
    const unsigned short* Bl = g_wtl + (size_t)widx*512*512;
    bool three = (mode == 0);

    int n0   = blockIdx.x * 64;
    int row0 = blockIdx.y * 128;

    float acc[2][4][4];
    #pragma unroll
    for (int mi = 0; mi < 2; mi++)
        #pragma unroll
        for (int ni = 0; ni < 4; ni++)
            #pragma unroll
            for (int c = 0; c < 4; c++) acc[mi][ni][c] = 0.f;

    auto issue_chunk = [&](int kb, uint32_t bufo) {
        int kbase = kb * 64;
        #pragma unroll
        for (int i = 0; i < 8; i++) {
            int idx = i*256 + tid;
            int a = idx >> 10;
            int rem = idx & 1023;
            int row = rem >> 3, q8 = rem & 7;
            const unsigned short* srcp = a ? Al : Ah;
            CP_ASYNC16(sbase + bufo + (a ? GM_AL : GM_AH) + row*144 + q8*16,
                       &srcp[(size_t)(row0+row)*512 + kbase + q8*8]);
        }
        #pragma unroll
        for (int i = 0; i < 2; i++) {
            int idx = i*256 + tid;
            int row = idx >> 3, q8 = idx & 7;
            CP_ASYNC16(sbase + bufo + GM_BH + row*144 + q8*16,
                       &Bh[(size_t)(n0+row)*512 + kbase + q8*8]);
        }
        if (three) {
            #pragma unroll
            for (int i = 0; i < 2; i++) {
                int idx = i*256 + tid;
                int row = idx >> 3, q8 = idx & 7;
                CP_ASYNC16(sbase + bufo + GM_BL + row*144 + q8*16,
                           &Bl[(size_t)(n0+row)*512 + kbase + q8*8]);
            }
        }
        CP_COMMIT();
    };

    issue_chunk(0, 0);

    for (int kb = 0; kb < 8; kb++) {
        uint32_t bufo = (kb & 1) ? GM_BUF : 0;
        CP_WAIT0();
        __syncthreads();
        if (kb + 1 < 8)
            issue_chunk(kb + 1, ((kb + 1) & 1) ? GM_BUF : 0);

        #pragma unroll
        for (int ks = 0; ks < 4; ks++) {
            uint32_t a_hi[2][4], a_lo[2][4], b_hi[8], b_lo[8];
            #pragma unroll
            for (int mi = 0; mi < 2; mi++) {
                int row = wm*32 + mi*16 + (lane & 15);
                int kcol = ks*16 + ((lane >> 4) << 3);
                uint32_t off = bufo + (uint32_t)(row*144 + kcol*2);
                ldsm_x4(a_hi[mi][0], a_hi[mi][1], a_hi[mi][2], a_hi[mi][3],
                        sbase + GM_AH + off);
                ldsm_x4(a_lo[mi][0], a_lo[mi][1], a_lo[mi][2], a_lo[mi][3],
                        sbase + GM_AL + off);
            }
            #pragma unroll
            for (int g = 0; g < 2; g++) {
                int rr = lane & 7;
                int hk = (lane >> 3) & 1;
                int hn = (lane >> 4) & 1;
                int nrow = wn*32 + g*16 + hn*8 + rr;
                int kcol = ks*16 + hk*8;
                uint32_t off = bufo + (uint32_t)(nrow*144 + kcol*2);
                ldsm_x4(b_hi[g*4+0], b_hi[g*4+1], b_hi[g*4+2], b_hi[g*4+3],
                        sbase + GM_BH + off);
                if (three)
                    ldsm_x4(b_lo[g*4+0], b_lo[g*4+1], b_lo[g*4+2], b_lo[g*4+3],
                            sbase + GM_BL + off);
            }
            #pragma unroll
            for (int mi = 0; mi < 2; mi++)
                #pragma unroll
                for (int ni = 0; ni < 4; ni++)
                    mma_f16(acc[mi][ni], a_hi[mi], &b_hi[ni*2]);
            #pragma unroll
            for (int mi = 0; mi < 2; mi++)
                #pragma unroll
                for (int ni = 0; ni < 4; ni++)
                    mma_f16(acc[mi][ni], a_lo[mi], &b_hi[ni*2]);
            if (three) {
                #pragma unroll
                for (int mi = 0; mi < 2; mi++)
                    #pragma unroll
                    for (int ni = 0; ni < 4; ni++)
                        mma_f16(acc[mi][ni], a_hi[mi], &b_lo[ni*2]);
            }
        }
    }

    float scale = (mode == 0) ? 0.125f * LOG2E_F : 1.f;
    #pragma unroll
    for (int mi = 0; mi < 2; mi++) {
        #pragma unroll
        for (int ni = 0; ni < 4; ni++) {
            int nl = wn*32 + ni*8 + (lane & 3)*2;
            float b0 = bias[n0 + nl], b1 = bias[n0 + nl + 1];
            #pragma unroll
            for (int half = 0; half < 2; half++) {
                int m = row0 + wm*32 + mi*16 + (lane >> 2) + half*8;
                float ox = (acc[mi][ni][half*2+0] + b0) * scale;
                float oy = (acc[mi][ni][half*2+1] + b1) * scale;
                if (mode < 3) {
                    int enc = m >> 12, b = (m >> 10) & 3, l = m & 1023;
                    int h = n0 >> 6;
                    size_t idx = ((((size_t)(enc*B_ + b))*H_ + h)*L_ + l)*HD_ + nl;
                    if (mode == 0) {
                        uint32_t hi, lo; split2(ox, oy, hi, lo);
                        *(uint32_t*)&g_qh[idx] = hi;
                        *(uint32_t*)&g_ql[idx] = lo;
                    } else if (mode == 1) {
                        *(uint32_t*)&g_kh[idx] = pack2h(ox, oy);
                    } else {
                        *(uint32_t*)&g_vh[idx] = pack2h(ox, oy);
                    }
                } else {
                    float2 o; o.x = ox; o.y = oy;
                    *(float2*)&outp[(size_t)m*D_ + nl + n0] = o;
                }
            }
        }
    }
}

// ===========================================================================
// Flash attention: QK 2-term (Q hi/lo x K single), PV 1-term (P single x V).
//   grid (16 qtiles, 32 b*h, 2 dirs), 128 threads (4 warps).
// KV stage: KH 0, VH 9216 -> 18432/stage, 2 stages. Q at 36864 (QH+QL).
// ===========================================================================
#define AT_BUF  18432
#define AT_KH   0
#define AT_VH   9216
#define AT_Q    36864
#define AT_SMEM 55296

__global__ __launch_bounds__(128) void attn_mma_kernel()
{
    extern __shared__ __align__(16) unsigned char smem[];
    uint32_t sbase = smem_u32(smem);

    int tid = threadIdx.x;
    int wid = tid >> 5, lane = tid & 31;
    int r = lane >> 2, cq = lane & 3;

    int qt = blockIdx.x, bh = blockIdx.y, dir = blockIdx.z;
    int b = bh >> 3, h = bh & 7;
    int enc_q = dir, enc_kv = 1 - dir;

    size_t qoff  = ((size_t)((enc_q *B_ + b)*H_ + h))*L_*HD_;
    size_t kvoff = ((size_t)((enc_kv*B_ + b)*H_ + h))*L_*HD_;
    const unsigned short* Qh = g_qh + qoff;
    const unsigned short* Ql = g_ql + qoff;
    const unsigned short* Kh = g_kh + kvoff;
    const unsigned short* Vh = g_vh + kvoff;
    const unsigned short* mb = g_mb + ((size_t)dir*B_ + b)*L_*L_;
    int q0 = qt * 64;

    // ---- Q cp.async ----
    #pragma unroll
    for (int i = 0; i < 8; i++) {
        int idx = i*128 + tid;
        int a = idx >> 9;
        int rem = idx & 511;
        int row = rem >> 3, q8 = rem & 7;
        const unsigned short* srcp = a ? Ql : Qh;
        CP_ASYNC16(sbase + AT_Q + (a ? 9216 : 0) + row*144 + q8*16,
                   &srcp[(size_t)(q0+row)*HD_ + q8*8]);
    }
    CP_COMMIT();
    CP_WAIT0();
    __syncthreads();

    auto issue_kv = [&](int t, uint32_t bufo) {
        int k0 = t * 64;
        #pragma unroll
        for (int i = 0; i < 8; i++) {
            int idx = i*128 + tid;
            int a = idx >> 9;                  // 0=KH 1=VH
            int rem = idx & 511;
            int row = rem >> 3, q8 = rem & 7;
            const unsigned short* srcp = a ? Vh : Kh;
            int dsto = a ? AT_VH : AT_KH;
            CP_ASYNC16(sbase + bufo + dsto + row*144 + q8*16,
                       &srcp[(size_t)(k0+row)*HD_ + q8*8]);
        }
        CP_COMMIT();
    };

    issue_kv(0, 0);

    // ---- Q A-fragments resident in regs ----
    uint32_t aq_h[4][4], aq_l[4][4];
    #pragma unroll
    for (int ks = 0; ks < 4; ks++) {
        int row = wid*16 + (lane & 15);
        int kcol = ks*16 + ((lane >> 4) << 3);
        uint32_t off = (uint32_t)(row*144 + kcol*2);
        ldsm_x4(aq_h[ks][0], aq_h[ks][1], aq_h[ks][2], aq_h[ks][3],
                sbase + AT_Q + off);
        ldsm_x4(aq_l[ks][0], aq_l[ks][1], aq_l[ks][2], aq_l[ks][3],
                sbase + AT_Q + 9216 + off);
    }

    float o_acc[8][4];
    #pragma unroll
    for (int nt = 0; nt < 8; nt++)
        #pragma unroll
        for (int c = 0; c < 4; c++) o_acc[nt][c] = 0.f;
    float m0r = -3.0e38f, m1r = -3.0e38f, l0r = 0.f, l1r = 0.f;

    int qg0 = q0 + wid*16 + r;
    int qg1 = qg0 + 8;
    const unsigned short* mb0 = mb + (size_t)qg0*L_ + cq*2;
    const unsigned short* mb1 = mb + (size_t)qg1*L_ + cq*2;

    for (int t = 0; t < 16; t++) {
        int k0 = t * 64;
        uint32_t bufo = (t & 1) ? AT_BUF : 0;
        CP_WAIT0();
        __syncthreads();
        if (t + 1 < 16)
            issue_kv(t + 1, ((t + 1) & 1) ? AT_BUF : 0);

        float2 mbv0[8], mbv1[8];
        #pragma unroll
        for (int nt = 0; nt < 8; nt++) {
            int cc = k0 + nt*8;
            mbv0[nt] = h2unpack(*(const uint32_t*)&mb0[cc]);
            mbv1[nt] = h2unpack(*(const uint32_t*)&mb1[cc]);
        }

        // ---- S = Q K^T (2-term: q hi/lo x k single) ----
        float s_acc[8][4];
        #pragma unroll
        for (int nt = 0; nt < 8; nt++)
            #pragma unroll
            for (int c = 0; c < 4; c++) s_acc[nt][c] = 0.f;

        #pragma unroll
        for (int ks = 0; ks < 4; ks++) {
            #pragma unroll
            for (int g = 0; g < 4; g++) {
                uint32_t bk[4];
                int rr = lane & 7;
                int hk = (lane >> 3) & 1;
                int hn = (lane >> 4) & 1;
                int nrow = g*16 + hn*8 + rr;
                int kcol = ks*16 + hk*8;
                uint32_t off = bufo + (uint32_t)(nrow*144 + kcol*2);
                ldsm_x4(bk[0], bk[1], bk[2], bk[3], sbase + AT_KH + off);
                int n0t = g*2, n1t = g*2 + 1;
                mma_f16(s_acc[n0t], aq_h[ks], &bk[0]);
                mma_f16(s_acc[n1t], aq_h[ks], &bk[2]);
                mma_f16(s_acc[n0t], aq_l[ks], &bk[0]);
                mma_f16(s_acc[n1t], aq_l[ks], &bk[2]);
            }
        }

        // ---- additive mask+bias (log2 domain) ----
        #pragma unroll
        for (int nt = 0; nt < 8; nt++) {
            s_acc[nt][0] += mbv0[nt].x;
            s_acc[nt][1] += mbv0[nt].y;
            s_acc[nt][2] += mbv1[nt].x;
            s_acc[nt][3] += mbv1[nt].y;
        }

        // ---- online softmax (base-2) ----
        float mx0 = -3.0e38f, mx1 = -3.0e38f;
        #pragma unroll
        for (int nt = 0; nt < 8; nt++) {
            mx0 = fmaxf(mx0, fmaxf(s_acc[nt][0], s_acc[nt][1]));
            mx1 = fmaxf(mx1, fmaxf(s_acc[nt][2], s_acc[nt][3]));
        }
        mx0 = fmaxf(mx0, __shfl_xor_sync(0xffffffffu, mx0, 1));
        mx0 = fmaxf(mx0, __shfl_xor_sync(0xffffffffu, mx0, 2));
        mx1 = fmaxf(mx1, __shfl_xor_sync(0xffffffffu, mx1, 1));
        mx1 = fmaxf(mx1, __shfl_xor_sync(0xffffffffu, mx1, 2));

        float mn0 = fmaxf(m0r, mx0);
        float mn1 = fmaxf(m1r, mx1);
        float c0 = ex2f(m0r - mn0);
        float c1 = ex2f(m1r - mn1);
        m0r = mn0; m1r = mn1;

        float rs0 = 0.f, rs1 = 0.f;
        #pragma unroll
        for (int nt = 0; nt < 8; nt++) {
            s_acc[nt][0] = ex2f(s_acc[nt][0] - m0r); rs0 += s_acc[nt][0];
            s_acc[nt][1] = ex2f(s_acc[nt][1] - m0r); rs0 += s_acc[nt][1];
            s_acc[nt][2] = ex2f(s_acc[nt][2] - m1r); rs1 += s_acc[nt][2];
            s_acc[nt][3] = ex2f(s_acc[nt][3] - m1r); rs1 += s_acc[nt][3];
        }
        rs0 += __shfl_xor_sync(0xffffffffu, rs0, 1);
        rs0 += __shfl_xor_sync(0xffffffffu, rs0, 2);
        rs1 += __shfl_xor_sync(0xffffffffu, rs1, 1);
        rs1 += __shfl_xor_sync(0xffffffffu, rs1, 2);
        l0r = l0r*c0 + rs0;
        l1r = l1r*c1 + rs1;

        #pragma unroll
        for (int nt = 0; nt < 8; nt++) {
            o_acc[nt][0] *= c0; o_acc[nt][1] *= c0;
            o_acc[nt][2] *= c1; o_acc[nt][3] *= c1;
        }

        // ---- O += P V (1-term: P single fp16 x V single) ----
        #pragma unroll
        for (int ks = 0; ks < 4; ks++) {
            int t0 = 2*ks, t1 = 2*ks + 1;
            uint32_t ap[4];
            ap[0] = pack2h(s_acc[t0][0], s_acc[t0][1]);
            ap[1] = pack2h(s_acc[t0][2], s_acc[t0][3]);
            ap[2] = pack2h(s_acc[t1][0], s_acc[t1][1]);
            ap[3] = pack2h(s_acc[t1][2], s_acc[t1][3]);
            #pragma unroll
            for (int g = 0; g < 4; g++) {
                uint32_t bv[4];
                int kk  = ks*16 + ((lane >> 3) & 1)*8 + (lane & 7);
                int hdo = g*16 + ((lane >> 4) & 1)*8;
                uint32_t off = bufo + (uint32_t)(kk*144 + hdo*2);
                ldsm_x4_t(bv[0], bv[1], bv[2], bv[3], sbase + AT_VH + off);
                int n0t = g*2, n1t = g*2 + 1;
                mma_f16(o_acc[n0t], ap, &bv[0]);
                mma_f16(o_acc[n1t], ap, &bv[2]);
            }
        }
    }

    // ---- finalize: ctx = O/l as fp16 hi/lo ----
    float inv0 = 1.f / l0r;
    float inv1 = 1.f / l1r;
    size_t base0 = ((size_t)(enc_q*B_ + b)*L_ + qg0)*D_ + h*64 + cq*2;
    size_t base1 = ((size_t)(enc_q*B_ + b)*L_ + qg1)*D_ + h*64 + cq*2;
    #pragma unroll
    for (int nt = 0; nt < 8; nt++) {
        uint32_t hi0, lo0, hi1, lo1;
        split2(o_acc[nt][0]*inv0, o_acc[nt][1]*inv0, hi0, lo0);
        split2(o_acc[nt][2]*inv1, o_acc[nt][3]*inv1, hi1, lo1);
        *(uint32_t*)&g_ch[base0 + nt*8] = hi0;
        *(uint32_t*)&g_cl[base0 + nt*8] = lo0;
        *(uint32_t*)&g_ch[base1 + nt*8] = hi1;
        *(uint32_t*)&g_cl[base1 + nt*8] = lo1;
    }
}

// ---------------------------------------------------------------------------
extern "C" void kernel_launch(void* const* d_in, const int* in_sizes, int n_in,
                              void* d_out, int out_size)
{
    const float* u_enc     = (const float*)d_in[0];
    const float* e_enc     = (const float*)d_in[1];
    const float* logit_bpp = (const float*)d_in[2];
    const void*  ue_mask   = d_in[3];
    const void*  eu_mask   = d_in[4];
    const float* wq_k = (const float*)d_in[5];
    const float* wq_b = (const float*)d_in[6];
    const float* wk_k = (const float*)d_in[7];
    const float* wk_b = (const float*)d_in[8];
    const float* wv_k = (const float*)d_in[9];
    const float* wv_b = (const float*)d_in[10];
    const float* wo_k = (const float*)d_in[11];
    const float* wo_b = (const float*)d_in[12];
    const float* bpp_w = (const float*)d_in[13];
    const float* bpp_b = (const float*)d_in[14];
    float* out = (float*)d_out;

    cudaFuncSetAttribute((const void*)attn_mma_kernel,
                         cudaFuncAttributeMaxDynamicSharedMemorySize, AT_SMEM);
    cudaFuncSetAttribute((const void*)gemm_mma_kernel,
                         cudaFuncAttributeMaxDynamicSharedMemorySize, GM_SMEM);

    // 0) mask dtype detection
    mask_detect_kernel<<<1, 256>>>((const unsigned int*)ue_mask);
    // 1) fused prep: maskbias + enc split + weight split (one launch)
    prep_kernel<<<5120, 256>>>(logit_bpp, bpp_w, bpp_b, ue_mask, eu_mask,
                               u_enc, e_enc, wq_k, wk_k, wv_k, wo_k);
    // 2) fused QKV projections (Q 3-term hi/lo; K,V 2-term single)
    gemm_mma_kernel<<<dim3(8, 64, 3), 256, GM_SMEM>>>(wq_b, wk_b, wv_b, wo_b,
                                                      nullptr, 0);
    // 3) fused attention (QK 2-term, PV 1-term)
    attn_mma_kernel<<<dim3(16, 32, 2), 128, AT_SMEM>>>();
    // 4) output projection (2-term) -> d_out
    gemm_mma_kernel<<<dim3(8, 64, 1), 256, GM_SMEM>>>(wq_b, wk_b, wv_b, wo_b,
                                                      out, 3);
}

// round 13
// speedup vs baseline: 1.5983x; 1.0489x over previous
#include <cuda_runtime.h>
#include <cuda_fp16.h>
#include <math.h>
#include <float.h>
#include <stdint.h>
#include <string.h>

#define B_  4
#define L_  1024
#define D_  512
#define H_  8
#define HD_ 64
#define PROJ_ELEMS (2*B_*H_*L_*HD_)   /* 4,194,304 */
#define MASK_ELEMS ((size_t)B_*L_*L_) /* 4,194,304 */
#define ENC_ELEMS  (8192*512)
#define LOG2E_F 1.4426950408889634f

// producer-split fp16 storage
__device__ unsigned short g_ah[ENC_ELEMS], g_al[ENC_ELEMS];      // [u;e] inputs
__device__ unsigned short g_wth[4*512*512], g_wtl[4*512*512];    // W^T, n-major
__device__ unsigned short g_qh[PROJ_ELEMS], g_ql[PROJ_ELEMS];    // Q hi/lo
__device__ unsigned short g_kh[PROJ_ELEMS];                      // K single fp16
__device__ unsigned short g_vh[PROJ_ELEMS];                      // V single fp16
__device__ unsigned short g_ch[PROJ_ELEMS], g_cl[PROJ_ELEMS];    // ctx hi/lo
__device__ unsigned short g_mb[2*B_*L_*L_];  // fp16 (bias*log2e) | -30000 masked
__device__ int g_mtype;

// ===========================================================================
// helpers
// ===========================================================================
__device__ __forceinline__ uint32_t smem_u32(const void* p) {
    uint32_t a;
    asm("{ .reg .u64 t; cvta.to.shared.u64 t, %1; cvt.u32.u64 %0, t; }"
        : "=r"(a) : "l"(p));
    return a;
}
#define CP_ASYNC16(saddr, gptr) \
    asm volatile("cp.async.ca.shared.global [%0], [%1], 16;" \
                 :: "r"(saddr), "l"(gptr))
#define CP_COMMIT() asm volatile("cp.async.commit_group;" ::: "memory")
#define CP_WAIT0()  asm volatile("cp.async.wait_group 0;" ::: "memory")

__device__ __forceinline__ float ex2f(float x) {
    float r;
    asm("ex2.approx.f32 %0, %1;" : "=f"(r) : "f"(x));
    return r;
}
__device__ __forceinline__ void ldsm_x4(uint32_t& r0, uint32_t& r1,
                                        uint32_t& r2, uint32_t& r3,
                                        uint32_t addr) {
    asm volatile("ldmatrix.sync.aligned.m8n8.x4.shared.b16 {%0,%1,%2,%3}, [%4];"
                 : "=r"(r0), "=r"(r1), "=r"(r2), "=r"(r3) : "r"(addr));
}
__device__ __forceinline__ void ldsm_x4_t(uint32_t& r0, uint32_t& r1,
                                          uint32_t& r2, uint32_t& r3,
                                          uint32_t addr) {
    asm volatile("ldmatrix.sync.aligned.m8n8.x4.trans.shared.b16 {%0,%1,%2,%3}, [%4];"
                 : "=r"(r0), "=r"(r1), "=r"(r2), "=r"(r3) : "r"(addr));
}
__device__ __forceinline__ void mma_f16(float* c, const uint32_t* a,
                                        const uint32_t* b) {
    asm volatile("mma.sync.aligned.m16n8k16.row.col.f32.f16.f16.f32 "
                 "{%0,%1,%2,%3}, {%4,%5,%6,%7}, {%8,%9}, {%0,%1,%2,%3};"
                 : "+f"(c[0]), "+f"(c[1]), "+f"(c[2]), "+f"(c[3])
                 : "r"(a[0]), "r"(a[1]), "r"(a[2]), "r"(a[3]),
                   "r"(b[0]), "r"(b[1]));
}
__device__ __forceinline__ unsigned short f2h_bits(float x) {
    __half h = __float2half_rn(x);
    unsigned short u; memcpy(&u, &h, 2); return u;
}
__device__ __forceinline__ float hbits2f(unsigned short u) {
    __half h; memcpy(&h, &u, 2); return __half2float(h);
}
__device__ __forceinline__ void split2(float x, float y, uint32_t& hi, uint32_t& lo) {
    unsigned short hx = f2h_bits(x), hy = f2h_bits(y);
    unsigned short lx = f2h_bits(x - hbits2f(hx));
    unsigned short ly = f2h_bits(y - hbits2f(hy));
    hi = (uint32_t)hx | ((uint32_t)hy << 16);
    lo = (uint32_t)lx | ((uint32_t)ly << 16);
}
__device__ __forceinline__ uint32_t pack2h(float x, float y) {
    return (uint32_t)f2h_bits(x) | ((uint32_t)f2h_bits(y) << 16);
}
__device__ __forceinline__ float2 h2unpack(uint32_t w) {
    __half2 h; memcpy(&h, &w, 4);
    return __half22float2(h);
}

// ===========================================================================
// Mask dtype detection
// ===========================================================================
__global__ void mask_detect_kernel(const unsigned int* __restrict__ m)
{
    __shared__ int viol[3];
    if (threadIdx.x < 3) viol[threadIdx.x] = 0;
    __syncthreads();
    int v0 = 0, v1 = 0, v2 = 0;
    for (int i = threadIdx.x; i < 16384; i += 256) {
        unsigned w = m[i];
        if (w > 1u) v0 = 1;
        if (w != 0u && w != 0x3F800000u) v1 = 1;
        if (w != 0u && w != 0x3F800000u && w != 0x00003F80u && w != 0x3F803F80u) v2 = 1;
    }
    if (v0) atomicOr(&viol[0], 1);
    if (v1) atomicOr(&viol[1], 1);
    if (v2) atomicOr(&viol[2], 1);
    __syncthreads();
    if (threadIdx.x == 0) {
        int t;
        if      (!viol[0]) t = 1;
        else if (!viol[1]) t = 2;
        else if (!viol[2]) t = 3;
        else               t = 0;
        g_mtype = t;
    }
}

// ===========================================================================
// Fused prep: blocks [0,2048) maskbias, [2048,4096) enc split, [4096,5120) wt.
// ===========================================================================
__global__ __launch_bounds__(256) void prep_kernel(
    const float* __restrict__ lb,
    const float* __restrict__ wp, const float* __restrict__ bp,
    const void* __restrict__ ue, const void* __restrict__ eu,
    const float* __restrict__ u, const float* __restrict__ e,
    const float* __restrict__ wq, const float* __restrict__ wk,
    const float* __restrict__ wv, const float* __restrict__ wo)
{
    __shared__ float s[32][33];
    int bx = blockIdx.x;
    int tid = threadIdx.x;
    int tx = tid & 31, ty = tid >> 5;

    if (bx < 2048) {
        int dir = bx >> 10;
        int q0 = ((bx >> 5) & 31) * 32;
        int k0 = (bx & 31) * 32;
        int mt = g_mtype;
        float w = wp[0] * LOG2E_F, bb = bp[0] * LOG2E_F;
        const void* msk = dir ? eu : ue;
        unsigned short* dst = g_mb + (size_t)dir * MASK_ELEMS;

        if (dir == 1) {
            #pragma unroll
            for (int i = ty; i < 32; i += 8)
                s[i][tx] = lb[(size_t)(k0+i)*L_ + q0 + tx];
            __syncthreads();
        }
        unsigned short mk = f2h_bits(-30000.0f);
        #pragma unroll
        for (int i = ty; i < 32; i += 8) {
            float bias;
            if (dir == 0) bias = fmaf(w, lb[(size_t)(q0+i)*L_ + k0 + tx], bb);
            else          bias = fmaf(w, s[tx][i], bb);
            unsigned short bh = f2h_bits(bias);
            size_t rowoff = (size_t)(q0+i)*L_ + k0 + tx;
            #pragma unroll
            for (int b = 0; b < B_; b++) {
                size_t idx = ((size_t)b << 20) + rowoff;
                bool mv;
                if      (mt == 1) mv = ((const int*)msk)[idx] != 0;
                else if (mt == 2) mv = ((const float*)msk)[idx] != 0.f;
                else if (mt == 3) mv = ((const unsigned short*)msk)[idx] != 0;
                else              mv = ((const unsigned char*)msk)[idx] != 0;
                dst[idx] = mv ? bh : mk;
            }
        }
    } else if (bx < 4096) {
        int idx = bx - 2048;
        int z = idx >> 10, blk = idx & 1023;
        const float* src = z ? e : u;
        size_t base4 = (size_t)z * (4096*512/4);
        size_t stride = 1024u * 256u;
        for (size_t i4 = (size_t)blk*256 + tid; i4 < 4096*512/4; i4 += stride) {
            float4 v = ((const float4*)src)[i4];
            uint32_t h01, l01, h23, l23;
            split2(v.x, v.y, h01, l01);
            split2(v.z, v.w, h23, l23);
            ((uint2*)g_ah)[base4 + i4] = make_uint2(h01, h23);
            ((uint2*)g_al)[base4 + i4] = make_uint2(l01, l23);
        }
    } else {
        int idx = bx - 4096;
        int z = idx >> 8, by = (idx >> 4) & 15, bxx = idx & 15;
        const float* src = (z == 0) ? wq : (z == 1) ? wk : (z == 2) ? wv : wo;
        int x  = bxx*32 + tx;
        int y0 = by*32;
        #pragma unroll
        for (int i = ty; i < 32; i += 8)
            s[i][tx] = src[(size_t)(y0+i)*512 + x];
        __syncthreads();
        size_t base = (size_t)z * 512*512;
        int ko = y0 + tx;
        #pragma unroll
        for (int i = ty; i < 32; i += 8) {
            float v = s[tx][i];
            unsigned short h = f2h_bits(v);
            unsigned short l = f2h_bits(v - hbits2f(h));
            size_t widx = base + (size_t)(bxx*32+i)*512 + ko;
            g_wth[widx] = h;
            g_wtl[widx] = l;
        }
    }
}

// ===========================================================================
// GEMM: 128M x 64N, K chunks 64, cp.async double-buffered (unchanged R12).
// ===========================================================================
#define GM_BUF  55296
#define GM_AH   0
#define GM_AL   18432
#define GM_BH   36864
#define GM_BL   46080
#define GM_SMEM 110592

__global__ __launch_bounds__(256) void gemm_mma_kernel(
    const float* __restrict__ bq, const float* __restrict__ bk,
    const float* __restrict__ bv, const float* __restrict__ bo,
    float* __restrict__ outp, int modebase)
{
    extern __shared__ __align__(16) unsigned char smem[];
    uint32_t sbase = smem_u32(smem);

    int tid = threadIdx.x;
    int wid = tid >> 5, lane = tid & 31;
    int wm = wid & 3, wn = wid >> 2;

    int mode = modebase + blockIdx.z;
    const float* bias;
    if      (mode == 0) bias = bq;
    else if (mode == 1) bias = bk;
    else if (mode == 2) bias = bv;
    else                bias = bo;

    const unsigned short* Ah = (mode < 3) ? g_ah : g_ch;
    const unsigned short* Al = (mode < 3) ? g_al : g_cl;
    int widx = (mode < 3) ? mode : 3;
    const unsigned short* Bh = g_wth + (size_t)widx*512*512;
    const unsigned short* Bl = g_wtl + (size_t)widx*512*512;
    bool three = (mode == 0);

    int n0   = blockIdx.x * 64;
    int row0 = blockIdx.y * 128;

    float acc[2][4][4];
    #pragma unroll
    for (int mi = 0; mi < 2; mi++)
        #pragma unroll
        for (int ni = 0; ni < 4; ni++)
            #pragma unroll
            for (int c = 0; c < 4; c++) acc[mi][ni][c] = 0.f;

    auto issue_chunk = [&](int kb, uint32_t bufo) {
        int kbase = kb * 64;
        #pragma unroll
        for (int i = 0; i < 8; i++) {
            int idx = i*256 + tid;
            int a = idx >> 10;
            int rem = idx & 1023;
            int row = rem >> 3, q8 = rem & 7;
            const unsigned short* srcp = a ? Al : Ah;
            CP_ASYNC16(sbase + bufo + (a ? GM_AL : GM_AH) + row*144 + q8*16,
                       &srcp[(size_t)(row0+row)*512 + kbase + q8*8]);
        }
        #pragma unroll
        for (int i = 0; i < 2; i++) {
            int idx = i*256 + tid;
            int row = idx >> 3, q8 = idx & 7;
            CP_ASYNC16(sbase + bufo + GM_BH + row*144 + q8*16,
                       &Bh[(size_t)(n0+row)*512 + kbase + q8*8]);
        }
        if (three) {
            #pragma unroll
            for (int i = 0; i < 2; i++) {
                int idx = i*256 + tid;
                int row = idx >> 3, q8 = idx & 7;
                CP_ASYNC16(sbase + bufo + GM_BL + row*144 + q8*16,
                           &Bl[(size_t)(n0+row)*512 + kbase + q8*8]);
            }
        }
        CP_COMMIT();
    };

    issue_chunk(0, 0);

    for (int kb = 0; kb < 8; kb++) {
        uint32_t bufo = (kb & 1) ? GM_BUF : 0;
        CP_WAIT0();
        __syncthreads();
        if (kb + 1 < 8)
            issue_chunk(kb + 1, ((kb + 1) & 1) ? GM_BUF : 0);

        #pragma unroll
        for (int ks = 0; ks < 4; ks++) {
            uint32_t a_hi[2][4], a_lo[2][4], b_hi[8], b_lo[8];
            #pragma unroll
            for (int mi = 0; mi < 2; mi++) {
                int row = wm*32 + mi*16 + (lane & 15);
                int kcol = ks*16 + ((lane >> 4) << 3);
                uint32_t off = bufo + (uint32_t)(row*144 + kcol*2);
                ldsm_x4(a_hi[mi][0], a_hi[mi][1], a_hi[mi][2], a_hi[mi][3],
                        sbase + GM_AH + off);
                ldsm_x4(a_lo[mi][0], a_lo[mi][1], a_lo[mi][2], a_lo[mi][3],
                        sbase + GM_AL + off);
            }
            #pragma unroll
            for (int g = 0; g < 2; g++) {
                int rr = lane & 7;
                int hk = (lane >> 3) & 1;
                int hn = (lane >> 4) & 1;
                int nrow = wn*32 + g*16 + hn*8 + rr;
                int kcol = ks*16 + hk*8;
                uint32_t off = bufo + (uint32_t)(nrow*144 + kcol*2);
                ldsm_x4(b_hi[g*4+0], b_hi[g*4+1], b_hi[g*4+2], b_hi[g*4+3],
                        sbase + GM_BH + off);
                if (three)
                    ldsm_x4(b_lo[g*4+0], b_lo[g*4+1], b_lo[g*4+2], b_lo[g*4+3],
                            sbase + GM_BL + off);
            }
            #pragma unroll
            for (int mi = 0; mi < 2; mi++)
                #pragma unroll
                for (int ni = 0; ni < 4; ni++)
                    mma_f16(acc[mi][ni], a_hi[mi], &b_hi[ni*2]);
            #pragma unroll
            for (int mi = 0; mi < 2; mi++)
                #pragma unroll
                for (int ni = 0; ni < 4; ni++)
                    mma_f16(acc[mi][ni], a_lo[mi], &b_hi[ni*2]);
            if (three) {
                #pragma unroll
                for (int mi = 0; mi < 2; mi++)
                    #pragma unroll
                    for (int ni = 0; ni < 4; ni++)
                        mma_f16(acc[mi][ni], a_hi[mi], &b_lo[ni*2]);
            }
        }
    }

    float scale = (mode == 0) ? 0.125f * LOG2E_F : 1.f;
    #pragma unroll
    for (int mi = 0; mi < 2; mi++) {
        #pragma unroll
        for (int ni = 0; ni < 4; ni++) {
            int nl = wn*32 + ni*8 + (lane & 3)*2;
            float b0 = bias[n0 + nl], b1 = bias[n0 + nl + 1];
            #pragma unroll
            for (int half = 0; half < 2; half++) {
                int m = row0 + wm*32 + mi*16 + (lane >> 2) + half*8;
                float ox = (acc[mi][ni][half*2+0] + b0) * scale;
                float oy = (acc[mi][ni][half*2+1] + b1) * scale;
                if (mode < 3) {
                    int enc = m >> 12, b = (m >> 10) & 3, l = m & 1023;
                    int h = n0 >> 6;
                    size_t idx = ((((size_t)(enc*B_ + b))*H_ + h)*L_ + l)*HD_ + nl;
                    if (mode == 0) {
                        uint32_t hi, lo; split2(ox, oy, hi, lo);
                        *(uint32_t*)&g_qh[idx] = hi;
                        *(uint32_t*)&g_ql[idx] = lo;
                    } else if (mode == 1) {
                        *(uint32_t*)&g_kh[idx] = pack2h(ox, oy);
                    } else {
                        *(uint32_t*)&g_vh[idx] = pack2h(ox, oy);
                    }
                } else {
                    float2 o; o.x = ox; o.y = oy;
                    *(float2*)&outp[(size_t)m*D_ + nl + n0] = o;
                }
            }
        }
    }
}

// ===========================================================================
// Flash attention v2: 32 q-rows per warp (2 m-tiles), 128 q-rows/CTA.
//   grid (8 qtiles, 32 b*h, 2 dirs), 128 threads (4 warps).
//   QK 2-term (Q hi/lo x K single), PV 1-term. B-frags shared across m-tiles.
// KV ring 2 x 18432 at [0, 36864); Q (QH+QL, 128 rows) at 36864..73728.
// ===========================================================================
#define AT_BUF  18432
#define AT_KH   0
#define AT_VH   9216
#define AT_Q    36864
#define AT_QL   (36864 + 18432)
#define AT_SMEM 73728

__global__ __launch_bounds__(128) void attn_mma_kernel()
{
    extern __shared__ __align__(16) unsigned char smem[];
    uint32_t sbase = smem_u32(smem);

    int tid = threadIdx.x;
    int wid = tid >> 5, lane = tid & 31;
    int r = lane >> 2, cq = lane & 3;

    int qt = blockIdx.x, bh = blockIdx.y, dir = blockIdx.z;
    int b = bh >> 3, h = bh & 7;
    int enc_q = dir, enc_kv = 1 - dir;

    size_t qoff  = ((size_t)((enc_q *B_ + b)*H_ + h))*L_*HD_;
    size_t kvoff = ((size_t)((enc_kv*B_ + b)*H_ + h))*L_*HD_;
    const unsigned short* Qh = g_qh + qoff;
    const unsigned short* Ql = g_ql + qoff;
    const unsigned short* Kh = g_kh + kvoff;
    const unsigned short* Vh = g_vh + kvoff;
    const unsigned short* mb = g_mb + ((size_t)dir*B_ + b)*L_*L_;
    int q0 = qt * 128;

    // ---- Q cp.async: 128 rows x 8 uint4 x 2 arrays = 2048 / 128 = 16 iters
    #pragma unroll
    for (int i = 0; i < 16; i++) {
        int idx = i*128 + tid;
        int a = idx >> 10;
        int rem = idx & 1023;
        int row = rem >> 3, q8 = rem & 7;
        const unsigned short* srcp = a ? Ql : Qh;
        CP_ASYNC16(sbase + (a ? AT_QL : AT_Q) + row*144 + q8*16,
                   &srcp[(size_t)(q0+row)*HD_ + q8*8]);
    }
    CP_COMMIT();
    CP_WAIT0();
    __syncthreads();

    auto issue_kv = [&](int t, uint32_t bufo) {
        int k0 = t * 64;
        #pragma unroll
        for (int i = 0; i < 8; i++) {
            int idx = i*128 + tid;
            int a = idx >> 9;
            int rem = idx & 511;
            int row = rem >> 3, q8 = rem & 7;
            const unsigned short* srcp = a ? Vh : Kh;
            int dsto = a ? AT_VH : AT_KH;
            CP_ASYNC16(sbase + bufo + dsto + row*144 + q8*16,
                       &srcp[(size_t)(k0+row)*HD_ + q8*8]);
        }
        CP_COMMIT();
    };

    issue_kv(0, 0);

    // ---- Q hi A-fragments resident in regs; Q lo reloaded from smem ----
    uint32_t aq_h[2][4][4];
    #pragma unroll
    for (int mt = 0; mt < 2; mt++) {
        #pragma unroll
        for (int ks = 0; ks < 4; ks++) {
            int row = wid*32 + mt*16 + (lane & 15);
            int kcol = ks*16 + ((lane >> 4) << 3);
            uint32_t off = (uint32_t)(row*144 + kcol*2);
            ldsm_x4(aq_h[mt][ks][0], aq_h[mt][ks][1],
                    aq_h[mt][ks][2], aq_h[mt][ks][3], sbase + AT_Q + off);
        }
    }

    float o_acc[2][8][4];
    #pragma unroll
    for (int mt = 0; mt < 2; mt++)
        #pragma unroll
        for (int nt = 0; nt < 8; nt++)
            #pragma unroll
            for (int c = 0; c < 4; c++) o_acc[mt][nt][c] = 0.f;
    float mreg[2][2], lreg[2][2];
    #pragma unroll
    for (int mt = 0; mt < 2; mt++) {
        mreg[mt][0] = -3.0e38f; mreg[mt][1] = -3.0e38f;
        lreg[mt][0] = 0.f;      lreg[mt][1] = 0.f;
    }

    int qgw = q0 + wid*32 + r;   // mt row0 = qgw + mt*16, row1 = +8
    const unsigned short* mbrow[2][2];
    #pragma unroll
    for (int mt = 0; mt < 2; mt++) {
        mbrow[mt][0] = mb + (size_t)(qgw + mt*16)*L_ + cq*2;
        mbrow[mt][1] = mb + (size_t)(qgw + mt*16 + 8)*L_ + cq*2;
    }

    for (int t = 0; t < 16; t++) {
        int k0 = t * 64;
        uint32_t bufo = (t & 1) ? AT_BUF : 0;
        CP_WAIT0();
        __syncthreads();
        if (t + 1 < 16)
            issue_kv(t + 1, ((t + 1) & 1) ? AT_BUF : 0);

        // ---- S = Q K^T : shared B-frags across both m-tiles ----
        float s_acc[2][8][4];
        #pragma unroll
        for (int mt = 0; mt < 2; mt++)
            #pragma unroll
            for (int nt = 0; nt < 8; nt++)
                #pragma unroll
                for (int c = 0; c < 4; c++) s_acc[mt][nt][c] = 0.f;

        #pragma unroll
        for (int ks = 0; ks < 4; ks++) {
            // reload Q-lo frags for this ks (saves regs)
            uint32_t aq_l[2][4];
            #pragma unroll
            for (int mt = 0; mt < 2; mt++) {
                int row = wid*32 + mt*16 + (lane & 15);
                int kcol = ks*16 + ((lane >> 4) << 3);
                ldsm_x4(aq_l[mt][0], aq_l[mt][1], aq_l[mt][2], aq_l[mt][3],
                        sbase + AT_QL + (uint32_t)(row*144 + kcol*2));
            }
            #pragma unroll
            for (int g = 0; g < 4; g++) {
                uint32_t bk[4];
                int rr = lane & 7;
                int hk = (lane >> 3) & 1;
                int hn = (lane >> 4) & 1;
                int nrow = g*16 + hn*8 + rr;
                int kcol = ks*16 + hk*8;
                uint32_t off = bufo + (uint32_t)(nrow*144 + kcol*2);
                ldsm_x4(bk[0], bk[1], bk[2], bk[3], sbase + AT_KH + off);
                int n0t = g*2, n1t = g*2 + 1;
                #pragma unroll
                for (int mt = 0; mt < 2; mt++) {
                    mma_f16(s_acc[mt][n0t], aq_h[mt][ks], &bk[0]);
                    mma_f16(s_acc[mt][n1t], aq_h[mt][ks], &bk[2]);
                    mma_f16(s_acc[mt][n0t], aq_l[mt], &bk[0]);
                    mma_f16(s_acc[mt][n1t], aq_l[mt], &bk[2]);
                }
            }
        }

        // ---- mask+bias add + online softmax per m-tile ----
        #pragma unroll
        for (int mt = 0; mt < 2; mt++) {
            #pragma unroll
            for (int nt = 0; nt < 8; nt++) {
                int cc = k0 + nt*8;
                float2 b0v = h2unpack(*(const uint32_t*)&mbrow[mt][0][cc]);
                float2 b1v = h2unpack(*(const uint32_t*)&mbrow[mt][1][cc]);
                s_acc[mt][nt][0] += b0v.x;
                s_acc[mt][nt][1] += b0v.y;
                s_acc[mt][nt][2] += b1v.x;
                s_acc[mt][nt][3] += b1v.y;
            }

            float mx0 = -3.0e38f, mx1 = -3.0e38f;
            #pragma unroll
            for (int nt = 0; nt < 8; nt++) {
                mx0 = fmaxf(mx0, fmaxf(s_acc[mt][nt][0], s_acc[mt][nt][1]));
                mx1 = fmaxf(mx1, fmaxf(s_acc[mt][nt][2], s_acc[mt][nt][3]));
            }
            mx0 = fmaxf(mx0, __shfl_xor_sync(0xffffffffu, mx0, 1));
            mx0 = fmaxf(mx0, __shfl_xor_sync(0xffffffffu, mx0, 2));
            mx1 = fmaxf(mx1, __shfl_xor_sync(0xffffffffu, mx1, 1));
            mx1 = fmaxf(mx1, __shfl_xor_sync(0xffffffffu, mx1, 2));

            float mn0 = fmaxf(mreg[mt][0], mx0);
            float mn1 = fmaxf(mreg[mt][1], mx1);
            float c0 = ex2f(mreg[mt][0] - mn0);
            float c1 = ex2f(mreg[mt][1] - mn1);
            mreg[mt][0] = mn0; mreg[mt][1] = mn1;

            float rs0 = 0.f, rs1 = 0.f;
            #pragma unroll
            for (int nt = 0; nt < 8; nt++) {
                s_acc[mt][nt][0] = ex2f(s_acc[mt][nt][0] - mn0); rs0 += s_acc[mt][nt][0];
                s_acc[mt][nt][1] = ex2f(s_acc[mt][nt][1] - mn0); rs0 += s_acc[mt][nt][1];
                s_acc[mt][nt][2] = ex2f(s_acc[mt][nt][2] - mn1); rs1 += s_acc[mt][nt][2];
                s_acc[mt][nt][3] = ex2f(s_acc[mt][nt][3] - mn1); rs1 += s_acc[mt][nt][3];
            }
            rs0 += __shfl_xor_sync(0xffffffffu, rs0, 1);
            rs0 += __shfl_xor_sync(0xffffffffu, rs0, 2);
            rs1 += __shfl_xor_sync(0xffffffffu, rs1, 1);
            rs1 += __shfl_xor_sync(0xffffffffu, rs1, 2);
            lreg[mt][0] = lreg[mt][0]*c0 + rs0;
            lreg[mt][1] = lreg[mt][1]*c1 + rs1;

            #pragma unroll
            for (int nt = 0; nt < 8; nt++) {
                o_acc[mt][nt][0] *= c0; o_acc[mt][nt][1] *= c0;
                o_acc[mt][nt][2] *= c1; o_acc[mt][nt][3] *= c1;
            }
        }

        // ---- O += P V : shared V-frags across m-tiles ----
        #pragma unroll
        for (int ks = 0; ks < 4; ks++) {
            int t0 = 2*ks, t1 = 2*ks + 1;
            uint32_t ap[2][4];
            #pragma unroll
            for (int mt = 0; mt < 2; mt++) {
                ap[mt][0] = pack2h(s_acc[mt][t0][0], s_acc[mt][t0][1]);
                ap[mt][1] = pack2h(s_acc[mt][t0][2], s_acc[mt][t0][3]);
                ap[mt][2] = pack2h(s_acc[mt][t1][0], s_acc[mt][t1][1]);
                ap[mt][3] = pack2h(s_acc[mt][t1][2], s_acc[mt][t1][3]);
            }
            #pragma unroll
            for (int g = 0; g < 4; g++) {
                uint32_t bv[4];
                int kk  = ks*16 + ((lane >> 3) & 1)*8 + (lane & 7);
                int hdo = g*16 + ((lane >> 4) & 1)*8;
                uint32_t off = bufo + (uint32_t)(kk*144 + hdo*2);
                ldsm_x4_t(bv[0], bv[1], bv[2], bv[3], sbase + AT_VH + off);
                int n0t = g*2, n1t = g*2 + 1;
                #pragma unroll
                for (int mt = 0; mt < 2; mt++) {
                    mma_f16(o_acc[mt][n0t], ap[mt], &bv[0]);
                    mma_f16(o_acc[mt][n1t], ap[mt], &bv[2]);
                }
            }
        }
    }

    // ---- finalize: ctx = O/l as fp16 hi/lo ----
    #pragma unroll
    for (int mt = 0; mt < 2; mt++) {
        float inv0 = 1.f / lreg[mt][0];
        float inv1 = 1.f / lreg[mt][1];
        int row0g = qgw + mt*16;
        size_t base0 = ((size_t)(enc_q*B_ + b)*L_ + row0g)*D_ + h*64 + cq*2;
        size_t base1 = ((size_t)(enc_q*B_ + b)*L_ + row0g + 8)*D_ + h*64 + cq*2;
        #pragma unroll
        for (int nt = 0; nt < 8; nt++) {
            uint32_t hi0, lo0, hi1, lo1;
            split2(o_acc[mt][nt][0]*inv0, o_acc[mt][nt][1]*inv0, hi0, lo0);
            split2(o_acc[mt][nt][2]*inv1, o_acc[mt][nt][3]*inv1, hi1, lo1);
            *(uint32_t*)&g_ch[base0 + nt*8] = hi0;
            *(uint32_t*)&g_cl[base0 + nt*8] = lo0;
            *(uint32_t*)&g_ch[base1 + nt*8] = hi1;
            *(uint32_t*)&g_cl[base1 + nt*8] = lo1;
        }
    }
}

// ---------------------------------------------------------------------------
extern "C" void kernel_launch(void* const* d_in, const int* in_sizes, int n_in,
                              void* d_out, int out_size)
{
    const float* u_enc     = (const float*)d_in[0];
    const float* e_enc     = (const float*)d_in[1];
    const float* logit_bpp = (const float*)d_in[2];
    const void*  ue_mask   = d_in[3];
    const void*  eu_mask   = d_in[4];
    const float* wq_k = (const float*)d_in[5];
    const float* wq_b = (const float*)d_in[6];
    const float* wk_k = (const float*)d_in[7];
    const float* wk_b = (const float*)d_in[8];
    const float* wv_k = (const float*)d_in[9];
    const float* wv_b = (const float*)d_in[10];
    const float* wo_k = (const float*)d_in[11];
    const float* wo_b = (const float*)d_in[12];
    const float* bpp_w = (const float*)d_in[13];
    const float* bpp_b = (const float*)d_in[14];
    float* out = (float*)d_out;

    cudaFuncSetAttribute((const void*)attn_mma_kernel,
                         cudaFuncAttributeMaxDynamicSharedMemorySize, AT_SMEM);
    cudaFuncSetAttribute((const void*)gemm_mma_kernel,
                         cudaFuncAttributeMaxDynamicSharedMemorySize, GM_SMEM);

    // 0) mask dtype detection
    mask_detect_kernel<<<1, 256>>>((const unsigned int*)ue_mask);
    // 1) fused prep
    prep_kernel<<<5120, 256>>>(logit_bpp, bpp_w, bpp_b, ue_mask, eu_mask,
                               u_enc, e_enc, wq_k, wk_k, wv_k, wo_k);
    // 2) fused QKV projections
    gemm_mma_kernel<<<dim3(8, 64, 3), 256, GM_SMEM>>>(wq_b, wk_b, wv_b, wo_b,
                                                      nullptr, 0);
    // 3) fused attention (128 q-rows/CTA, shared B-frags)
    attn_mma_kernel<<<dim3(8, 32, 2), 128, AT_SMEM>>>();
    // 4) output projection -> d_out
    gemm_mma_kernel<<<dim3(8, 64, 1), 256, GM_SMEM>>>(wq_b, wk_b, wv_b, wo_b,
                                                      out, 3);
}